// round 6
// baseline (speedup 1.0000x reference)
#include <cuda_runtime.h>
#include <cuda_bf16.h>
#include <math.h>

// Problem constants (fixed by reference setup_inputs)
#define B_  8
#define L_  128
#define H_  768
#define P_  16
#define NCH 17          // 16 perspectives + plain cosine channel
#define OUTD 102
#define EPSF 1e-8f
#define NEGINF (-1e30f)
#define TT 8            // token tile for attention kernel

// ---------------- scratch (static device memory; no allocation) ----------------
__device__ float g_c[2][B_*L_*H_];      // masked contexts  (side 0 = seq1, side 1 = seq2)
__device__ float g_n[2][B_*L_];         // plain L2 norms
__device__ float g_nw[2][B_*L_*P_];     // w_mp-weighted norms
__device__ float g_S[B_*NCH*L_*L_];     // normalized mm (p<16) and cos_sim (p==16)
__device__ float g_attS[2][B_*L_*H_];   // att sums -> overwritten by softmax => att_mean
__device__ float g_attM[2][B_*L_*H_];   // att maxes
__device__ int   g_len[2][B_];

// ---------------- lengths ----------------
__global__ void k_len(const float* __restrict__ m1, const float* __restrict__ m2) {
    int t = threadIdx.x;
    if (t < 16) {
        int s = t >> 3, b = t & 7;
        const float* mk = s ? m2 : m1;
        float acc = 0.f;
        for (int j = 0; j < L_; j++) acc += mk[b*L_ + j];
        g_len[s][b] = (int)(acc + 0.5f);
    }
}

// ---------------- masked context + norms ----------------
__global__ __launch_bounds__(256) void k_prep(
    const float* __restrict__ ctx1, const float* __restrict__ m1,
    const float* __restrict__ ctx2, const float* __restrict__ m2,
    const float* __restrict__ w_mp)
{
    int i = blockIdx.x, b = blockIdx.y, s = blockIdx.z;
    const float* ctx = s ? ctx2 : ctx1;
    const float* mk  = s ? m2   : m1;
    __shared__ float cs[H_];
    float m = mk[b*L_ + i];
    int tid = threadIdx.x;
    float* cdst = g_c[s] + (size_t)(b*L_ + i) * H_;
    const float* csrc = ctx + (size_t)(b*L_ + i) * H_;
    for (int h = tid; h < H_; h += 256) {
        float v = csrc[h] * m;
        cs[h] = v;
        cdst[h] = v;
    }
    __syncthreads();
    int w = tid >> 5, lane = tid & 31;
    for (int t = w; t < NCH; t += 8) {
        float acc = 0.f;
        #pragma unroll
        for (int k = 0; k < H_/32; k++) {
            int h = lane + 32*k;
            float c = cs[h];
            float x = (t < P_) ? w_mp[t*H_ + h] * c : c;
            acc = fmaf(x, x, acc);
        }
        #pragma unroll
        for (int o = 16; o; o >>= 1) acc += __shfl_xor_sync(0xffffffffu, acc, o);
        if (lane == 0) {
            if (t == P_) g_n[s][b*L_ + i] = sqrtf(acc);
            else         g_nw[s][(b*L_ + i)*P_ + t] = sqrtf(acc);
        }
    }
}

// ---------------- 17-channel pairwise GEMM + normalization ----------------
// grid (4, NCH, B): blockIdx.x -> 64x64 tile, y -> channel p, z -> batch b
__global__ __launch_bounds__(256) void k_gemm(const float* __restrict__ w_mp) {
    int b = blockIdx.z, p = blockIdx.y;
    int ti = (blockIdx.x >> 1) * 64;
    int tj = (blockIdx.x & 1) * 64;
    const float* A  = g_c[0] + (size_t)b * L_ * H_;
    const float* Bm = g_c[1] + (size_t)b * L_ * H_;
    __shared__ float As[16][64];
    __shared__ float Bs[16][64];
    int tid = threadIdx.x;
    int lr = tid >> 2;            // 0..63  (tile row for loading)
    int lc = (tid & 3) << 2;      // 0,4,8,12 (k offset)
    int row = (tid >> 4) << 2;    // 0..60
    int col = (tid & 15) << 2;    // 0..60
    float acc[4][4];
    #pragma unroll
    for (int u = 0; u < 4; u++)
        #pragma unroll
        for (int v = 0; v < 4; v++) acc[u][v] = 0.f;

    const bool weighted = (p < P_);
    const float* wp = w_mp + p * H_;   // only read when weighted

    for (int k0 = 0; k0 < H_; k0 += 16) {
        float4 a4 = *(const float4*)(A  + (size_t)(ti + lr) * H_ + k0 + lc);
        float4 b4 = *(const float4*)(Bm + (size_t)(tj + lr) * H_ + k0 + lc);
        if (weighted) {
            float4 w4 = *(const float4*)(wp + k0 + lc);
            a4.x *= w4.x; a4.y *= w4.y; a4.z *= w4.z; a4.w *= w4.w;
            b4.x *= w4.x; b4.y *= w4.y; b4.z *= w4.z; b4.w *= w4.w;
        }
        __syncthreads();
        As[lc+0][lr] = a4.x; As[lc+1][lr] = a4.y; As[lc+2][lr] = a4.z; As[lc+3][lr] = a4.w;
        Bs[lc+0][lr] = b4.x; Bs[lc+1][lr] = b4.y; Bs[lc+2][lr] = b4.z; Bs[lc+3][lr] = b4.w;
        __syncthreads();
        #pragma unroll
        for (int k = 0; k < 16; k++) {
            float4 ra = *(const float4*)&As[k][row];
            float4 rb = *(const float4*)&Bs[k][col];
            float av[4] = {ra.x, ra.y, ra.z, ra.w};
            float bv[4] = {rb.x, rb.y, rb.z, rb.w};
            #pragma unroll
            for (int u = 0; u < 4; u++)
                #pragma unroll
                for (int v = 0; v < 4; v++)
                    acc[u][v] = fmaf(av[u], bv[v], acc[u][v]);
        }
    }

    // epilogue: normalize
    float dl[4], dr[4];
    if (weighted) {
        #pragma unroll
        for (int u = 0; u < 4; u++) dl[u] = g_nw[0][(b*L_ + ti + row + u)*P_ + p];
        #pragma unroll
        for (int v = 0; v < 4; v++) dr[v] = g_nw[1][(b*L_ + tj + col + v)*P_ + p];
        #pragma unroll
        for (int u = 0; u < 4; u++)
            #pragma unroll
            for (int v = 0; v < 4; v++)
                acc[u][v] /= fmaxf(dl[u] * dr[v], EPSF);   // clip on PRODUCT (ref)
    } else {
        #pragma unroll
        for (int u = 0; u < 4; u++) dl[u] = fmaxf(g_n[0][b*L_ + ti + row + u], EPSF);
        #pragma unroll
        for (int v = 0; v < 4; v++) dr[v] = fmaxf(g_n[1][b*L_ + tj + col + v], EPSF);
        #pragma unroll
        for (int u = 0; u < 4; u++)
            #pragma unroll
            for (int v = 0; v < 4; v++)
                acc[u][v] /= (dl[u] * dr[v]);              // clip each norm (ref)
    }
    float* Sout = g_S + ((size_t)(b*NCH + p)) * L_ * L_;
    #pragma unroll
    for (int u = 0; u < 4; u++) {
        float4 st = make_float4(acc[u][0], acc[u][1], acc[u][2], acc[u][3]);
        *(float4*)(Sout + (size_t)(ti + row + u) * L_ + tj + col) = st;
    }
}

// ---------------- masked max/mean reductions over S ----------------
// grid (NCH, B, 2): z=0 reduce over j (mask_2) -> side-1 tokens; z=1 reduce over i (mask_1)
__global__ __launch_bounds__(128) void k_reduce(
    const float* __restrict__ m1, const float* __restrict__ m2,
    float* __restrict__ out)
{
    int p = blockIdx.x, b = blockIdx.y, z = blockIdx.z;
    const float* Sp = g_S + ((size_t)(b*NCH + p)) * L_ * L_;
    const float* mk = z ? m1 : m2;                 // mask over reduced axis
    __shared__ float msk[L_];
    int tid = threadIdx.x;
    if (tid < L_) msk[tid] = mk[b*L_ + tid];
    __syncthreads();
    float cnt = (float)g_len[z ? 0 : 1][b];
    int w = tid >> 5, lane = tid & 31;
    for (int t0 = 0; t0 < 32; t0++) {
        int t = w*32 + t0;
        float mx = NEGINF, sm = 0.f;
        #pragma unroll
        for (int k = 0; k < 4; k++) {
            int u = lane + 32*k;
            float v = z ? Sp[(size_t)u * L_ + t] : Sp[(size_t)t * L_ + u];
            if (msk[u] != 0.f) { mx = fmaxf(mx, v); sm += v; }
        }
        #pragma unroll
        for (int o = 16; o; o >>= 1) {
            mx = fmaxf(mx, __shfl_xor_sync(0xffffffffu, mx, o));
            sm += __shfl_xor_sync(0xffffffffu, sm, o);
        }
        if (lane == 0) {
            float mean = sm / fmaxf(cnt, EPSF);
            float* o_ = out + ((size_t)(b*2 + z)*L_ + t) * OUTD;
            if (p == P_) { o_[0] = mx; o_[1] = mean; }
            else         { o_[36 + p] = mx; o_[52 + p] = mean; }
        }
    }
}

// ---------------- attention sums and maxes ----------------
// grid (L/TT, B, 2): s=0 -> per-i over j with c2; s=1 -> per-j over i with c1
__global__ __launch_bounds__(256) void k_att() {
    int tb = blockIdx.x, b = blockIdx.y, s = blockIdx.z;
    int other = 1 - s;
    int lenO = g_len[other][b];
    const float* C = g_c[other] + (size_t)b * L_ * H_;
    const float* Scos = g_S + ((size_t)(b*NCH + P_)) * L_ * L_;
    __shared__ float cw[TT][L_];
    int tid = threadIdx.x;
    for (int idx = tid; idx < TT*L_; idx += 256) {
        int tt = idx >> 7, u = idx & (L_-1);
        int t = tb*TT + tt;
        cw[tt][u] = (s == 0) ? Scos[(size_t)t * L_ + u] : Scos[(size_t)u * L_ + t];
    }
    __syncthreads();

    float sm[TT][3], mx[TT][3];
    #pragma unroll
    for (int tt = 0; tt < TT; tt++)
        #pragma unroll
        for (int q = 0; q < 3; q++) { sm[tt][q] = 0.f; mx[tt][q] = NEGINF; }

    for (int u = 0; u < lenO; u++) {
        float c0 = C[(size_t)u*H_ + tid];
        float c1 = C[(size_t)u*H_ + tid + 256];
        float c2 = C[(size_t)u*H_ + tid + 512];
        #pragma unroll
        for (int tt = 0; tt < TT; tt++) {
            float w = cw[tt][u];
            float p0 = w * c0, p1 = w * c1, p2 = w * c2;
            sm[tt][0] += p0; sm[tt][1] += p1; sm[tt][2] += p2;
            mx[tt][0] = fmaxf(mx[tt][0], p0);
            mx[tt][1] = fmaxf(mx[tt][1], p1);
            mx[tt][2] = fmaxf(mx[tt][2], p2);
        }
    }
    #pragma unroll
    for (int tt = 0; tt < TT; tt++) {
        int t = tb*TT + tt;
        size_t base = ((size_t)(b*L_ + t)) * H_;
        #pragma unroll
        for (int q = 0; q < 3; q++) {
            int h = tid + q*256;
            g_attS[s][base + h] = sm[tt][q];
            g_attM[s][base + h] = mx[tt][q];
        }
    }
}

// ---------------- softmax over H (in place on g_attS -> att_mean) ----------------
__global__ __launch_bounds__(256) void k_softmax(
    const float* __restrict__ m1, const float* __restrict__ m2)
{
    int t = blockIdx.x, b = blockIdx.y, s = blockIdx.z;
    float* v = g_attS[s] + ((size_t)(b*L_ + t)) * H_;
    const float* mk = s ? m2 : m1;
    int tid = threadIdx.x;
    float m = mk[b*L_ + t];
    if (m == 0.f) {
        for (int h = tid; h < H_; h += 256) v[h] = 1.f / (float)H_;
        return;
    }
    __shared__ float red[8];
    float loc[3];
    float mx = NEGINF;
    #pragma unroll
    for (int q = 0; q < 3; q++) { loc[q] = v[tid + q*256]; mx = fmaxf(mx, loc[q]); }
    int w = tid >> 5, lane = tid & 31;
    #pragma unroll
    for (int o = 16; o; o >>= 1) mx = fmaxf(mx, __shfl_xor_sync(0xffffffffu, mx, o));
    if (lane == 0) red[w] = mx;
    __syncthreads();
    mx = red[0];
    #pragma unroll
    for (int i = 1; i < 8; i++) mx = fmaxf(mx, red[i]);

    float sum = 0.f;
    #pragma unroll
    for (int q = 0; q < 3; q++) { loc[q] = expf(loc[q] - mx); sum += loc[q]; }
    #pragma unroll
    for (int o = 16; o; o >>= 1) sum += __shfl_xor_sync(0xffffffffu, sum, o);
    __syncthreads();
    if (lane == 0) red[w] = sum;
    __syncthreads();
    sum = 0.f;
    #pragma unroll
    for (int i = 0; i < 8; i++) sum += red[i];
    float inv = 1.f / sum;
    #pragma unroll
    for (int q = 0; q < 3; q++) v[tid + q*256] = loc[q] * inv;
}

// ---------------- per-token weighted cosines (ff, bf, att-mean, att-max) ----------------
__global__ __launch_bounds__(256) void k_final(
    const float* __restrict__ wff, const float* __restrict__ wfb,
    const float* __restrict__ watt, const float* __restrict__ wmatt,
    float* __restrict__ out)
{
    int t = blockIdx.x, b = blockIdx.y, s = blockIdx.z;
    int other = 1 - s;
    __shared__ float sa[H_];
    __shared__ float sv[4][H_];
    int tid = threadIdx.x;
    const float* a = g_c[s] + ((size_t)(b*L_ + t)) * H_;
    int lenO = g_len[other][b];
    int lp = lenO > 0 ? lenO - 1 : 0;
    const float* v_ff  = g_c[other] + ((size_t)(b*L_ + lp)) * H_;
    const float* v_bf  = g_c[other] + ((size_t)(b*L_ + 0)) * H_;
    const float* v_am  = g_attS[s] + ((size_t)(b*L_ + t)) * H_;
    const float* v_amx = g_attM[s] + ((size_t)(b*L_ + t)) * H_;
    for (int h = tid; h < H_; h += 256) {
        sa[h] = a[h];
        sv[0][h] = v_ff[h];
        sv[1][h] = v_bf[h];
        sv[2][h] = v_am[h];
        sv[3][h] = v_amx[h];
    }
    __syncthreads();

    int w = tid >> 5, lane = tid & 31;
    float* o_ = out + ((size_t)(b*2 + s)*L_ + t) * OUTD;
    for (int task = w; task < 68; task += 8) {
        int q = task / 17;
        int tt = task - q * 17;
        const float* W = (q == 0) ? wff : (q == 1) ? wfb : (q == 2) ? watt : wmatt;
        int base = (q == 0) ? 2 : (q == 1) ? 19 : (q == 2) ? 68 : 85;
        float sav = 0.f, saa = 0.f, svv = 0.f;
        #pragma unroll
        for (int k = 0; k < H_/32; k++) {
            int h = lane + 32*k;
            float av = sa[h], vv = sv[q][h];
            if (tt < P_) {
                float wt = W[tt*H_ + h];
                av *= wt; vv *= wt;
            }
            sav = fmaf(av, vv, sav);
            saa = fmaf(av, av, saa);
            svv = fmaf(vv, vv, svv);
        }
        #pragma unroll
        for (int o = 16; o; o >>= 1) {
            sav += __shfl_xor_sync(0xffffffffu, sav, o);
            saa += __shfl_xor_sync(0xffffffffu, saa, o);
            svv += __shfl_xor_sync(0xffffffffu, svv, o);
        }
        if (lane == 0) {
            float na = fmaxf(sqrtf(saa), EPSF);
            float nv = fmaxf(sqrtf(svv), EPSF);
            float r = sav / (na * nv);
            int col = (tt == P_) ? base : (base + 1 + tt);
            o_[col] = r;
        }
    }
}

// ---------------- launch ----------------
extern "C" void kernel_launch(void* const* d_in, const int* in_sizes, int n_in,
                              void* d_out, int out_size) {
    const float* c1    = (const float*)d_in[0];
    const float* m1    = (const float*)d_in[1];
    const float* c2    = (const float*)d_in[2];
    const float* m2    = (const float*)d_in[3];
    const float* wff   = (const float*)d_in[4];
    const float* wfb   = (const float*)d_in[5];
    const float* wmp   = (const float*)d_in[6];
    const float* watt  = (const float*)d_in[7];
    const float* wmatt = (const float*)d_in[8];
    float* out = (float*)d_out;
    (void)in_sizes; (void)n_in; (void)out_size;

    k_len    <<<1, 64>>>(m1, m2);
    k_prep   <<<dim3(L_, B_, 2), 256>>>(c1, m1, c2, m2, wmp);
    k_gemm   <<<dim3(4, NCH, B_), 256>>>(wmp);
    k_reduce <<<dim3(NCH, B_, 2), 128>>>(m1, m2, out);
    k_att    <<<dim3(L_/TT, B_, 2), 256>>>();
    k_softmax<<<dim3(L_, B_, 2), 256>>>(m1, m2);
    k_final  <<<dim3(L_, B_, 2), 256>>>(wff, wfb, watt, wmatt, out);
}

// round 7
// speedup vs baseline: 1.0063x; 1.0063x over previous
#include <cuda_runtime.h>
#include <math.h>

typedef unsigned long long ull;

// Problem constants (fixed by reference setup_inputs)
#define B_  8
#define L_  128
#define H_  768
#define P_  16
#define NCH 17          // 16 perspectives + plain cosine channel
#define OUTD 102
#define EPSF 1e-8f
#define NEGINF (-1e30f)
#define TT 16           // token tile for attention kernel

// ---------------- scratch (static device memory; no allocation) ----------------
__device__ float g_c[2][B_*L_*H_];      // masked contexts
__device__ float g_n[2][B_*L_];         // plain L2 norms
__device__ float g_nw[2][B_*L_*P_];     // w_mp-weighted norms
__device__ float g_S[B_*NCH*L_*L_];     // normalized mm (p<16) and cos_sim (p==16)
__device__ float g_attS[2][B_*L_*H_];   // att softmax (att_mean)
__device__ float g_attM[2][B_*L_*H_];   // att maxes
__device__ int   g_len[2][B_];

// ---------------- packed fp32x2 helpers ----------------
#define FMA2(d,a,b)    asm("fma.rn.f32x2 %0, %1, %2, %0;" : "+l"(d) : "l"(a), "l"(b))
#define MUL2(d,a,b)    asm("mul.rn.f32x2 %0, %1, %2;" : "=l"(d) : "l"(a), "l"(b))
#define PACK2(d,x)     asm("mov.b64 %0, {%1, %2};" : "=l"(d) : "f"(x), "f"(x))
#define UNPK2(lo,hi,v) asm("mov.b64 {%0, %1}, %2;" : "=f"(lo), "=f"(hi) : "l"(v))

__device__ __forceinline__ ull lds64(unsigned int addr) {
    ull v; asm volatile("ld.shared.b64 %0, [%1];" : "=l"(v) : "r"(addr)); return v;
}
__device__ __forceinline__ ull ldg64(const float* p) {
    ull v; asm volatile("ld.global.nc.b64 %0, [%1];" : "=l"(v) : "l"(p)); return v;
}

// ---------------- lengths ----------------
__global__ void k_len(const float* __restrict__ m1, const float* __restrict__ m2) {
    int t = threadIdx.x;
    if (t < 16) {
        int s = t >> 3, b = t & 7;
        const float* mk = s ? m2 : m1;
        float acc = 0.f;
        for (int j = 0; j < L_; j++) acc += mk[b*L_ + j];
        g_len[s][b] = (int)(acc + 0.5f);
    }
}

// ---------------- masked context + norms ----------------
__global__ __launch_bounds__(256) void k_prep(
    const float* __restrict__ ctx1, const float* __restrict__ m1,
    const float* __restrict__ ctx2, const float* __restrict__ m2,
    const float* __restrict__ w_mp)
{
    int i = blockIdx.x, b = blockIdx.y, s = blockIdx.z;
    const float* ctx = s ? ctx2 : ctx1;
    const float* mk  = s ? m2   : m1;
    __shared__ float cs[H_];
    float m = mk[b*L_ + i];
    int tid = threadIdx.x;
    float* cdst = g_c[s] + (size_t)(b*L_ + i) * H_;
    const float* csrc = ctx + (size_t)(b*L_ + i) * H_;
    for (int h = tid; h < H_; h += 256) {
        float v = csrc[h] * m;
        cs[h] = v;
        cdst[h] = v;
    }
    __syncthreads();
    int w = tid >> 5, lane = tid & 31;
    for (int t = w; t < NCH; t += 8) {
        float acc = 0.f;
        #pragma unroll
        for (int k = 0; k < H_/32; k++) {
            int h = lane + 32*k;
            float c = cs[h];
            float x = (t < P_) ? w_mp[t*H_ + h] * c : c;
            acc = fmaf(x, x, acc);
        }
        #pragma unroll
        for (int o = 16; o; o >>= 1) acc += __shfl_xor_sync(0xffffffffu, acc, o);
        if (lane == 0) {
            if (t == P_) g_n[s][b*L_ + i] = sqrtf(acc);
            else         g_nw[s][(b*L_ + i)*P_ + t] = sqrtf(acc);
        }
    }
}

// ---------------- 17-channel pairwise GEMM (packed f32x2) ----------------
// grid (2, NCH, B): 64x128 block tile, 4x8 per-thread micro-tile
__global__ __launch_bounds__(256) void k_gemm(const float* __restrict__ w_mp) {
    int b = blockIdx.z, p = blockIdx.y;
    int ti = blockIdx.x * 64;
    const float* A  = g_c[0] + (size_t)b * L_ * H_;
    const float* Bm = g_c[1] + (size_t)b * L_ * H_;
    __shared__ __align__(16) float As[16][64];
    __shared__ __align__(16) float Bs[16][128];
    int tid = threadIdx.x;
    int la_r = tid >> 2, la_k = (tid & 3) << 2;       // A-load:  row 0..63, koff {0,4,8,12}
    int lb_r = tid & 127, lb_k = (tid >> 7) << 3;     // B-load:  row 0..127, koff {0,8}
    int row  = (tid >> 4) << 2;                       // compute: 4 rows
    int cg2  = (tid & 15) << 1;                       // compute: col-pair base, q strides 32
    const bool weighted = (p < P_);
    const float* wp = w_mp + p * H_;

    ull acc[4][4];
    #pragma unroll
    for (int u = 0; u < 4; u++)
        #pragma unroll
        for (int q = 0; q < 4; q++) acc[u][q] = 0ull;

    unsigned int bs_b = (unsigned int)__cvta_generic_to_shared(&Bs[0][0]);

    for (int k0 = 0; k0 < H_; k0 += 16) {
        float4 a4  = *(const float4*)(A  + (size_t)(ti + la_r) * H_ + k0 + la_k);
        float4 b4a = *(const float4*)(Bm + (size_t)lb_r * H_ + k0 + lb_k);
        float4 b4b = *(const float4*)(Bm + (size_t)lb_r * H_ + k0 + lb_k + 4);
        if (weighted) {
            float4 w4 = *(const float4*)(wp + k0 + la_k);
            a4.x *= w4.x; a4.y *= w4.y; a4.z *= w4.z; a4.w *= w4.w;
            float4 wa = *(const float4*)(wp + k0 + lb_k);
            float4 wb = *(const float4*)(wp + k0 + lb_k + 4);
            b4a.x *= wa.x; b4a.y *= wa.y; b4a.z *= wa.z; b4a.w *= wa.w;
            b4b.x *= wb.x; b4b.y *= wb.y; b4b.z *= wb.z; b4b.w *= wb.w;
        }
        __syncthreads();
        As[la_k+0][la_r] = a4.x; As[la_k+1][la_r] = a4.y;
        As[la_k+2][la_r] = a4.z; As[la_k+3][la_r] = a4.w;
        Bs[lb_k+0][lb_r] = b4a.x; Bs[lb_k+1][lb_r] = b4a.y;
        Bs[lb_k+2][lb_r] = b4a.z; Bs[lb_k+3][lb_r] = b4a.w;
        Bs[lb_k+4][lb_r] = b4b.x; Bs[lb_k+5][lb_r] = b4b.y;
        Bs[lb_k+6][lb_r] = b4b.z; Bs[lb_k+7][lb_r] = b4b.w;
        __syncthreads();
        #pragma unroll
        for (int k = 0; k < 16; k++) {
            float4 ra = *(const float4*)&As[k][row];
            unsigned int bb = bs_b + (unsigned int)(((k << 7) + cg2) << 2);
            ull b0 = lds64(bb);
            ull b1 = lds64(bb + 32*4);
            ull b2 = lds64(bb + 64*4);
            ull b3 = lds64(bb + 96*4);
            float av[4] = {ra.x, ra.y, ra.z, ra.w};
            #pragma unroll
            for (int u = 0; u < 4; u++) {
                ull aa; PACK2(aa, av[u]);
                FMA2(acc[u][0], aa, b0);
                FMA2(acc[u][1], aa, b1);
                FMA2(acc[u][2], aa, b2);
                FMA2(acc[u][3], aa, b3);
            }
        }
    }

    // epilogue: normalize + store (cols = cg2 + 32q, pair)
    float* Sout = g_S + ((size_t)(b*NCH + p)) * L_ * L_;
    if (weighted) {
        float dl[4];
        #pragma unroll
        for (int u = 0; u < 4; u++) dl[u] = g_nw[0][(b*L_ + ti + row + u)*P_ + p];
        #pragma unroll
        for (int q = 0; q < 4; q++) {
            int col = cg2 + 32*q;
            float drx = g_nw[1][(b*L_ + col  )*P_ + p];
            float dry = g_nw[1][(b*L_ + col+1)*P_ + p];
            #pragma unroll
            for (int u = 0; u < 4; u++) {
                float lo, hi; UNPK2(lo, hi, acc[u][q]);
                lo /= fmaxf(dl[u] * drx, EPSF);    // clip on PRODUCT (ref)
                hi /= fmaxf(dl[u] * dry, EPSF);
                *(float2*)(Sout + (size_t)(ti + row + u) * L_ + col) = make_float2(lo, hi);
            }
        }
    } else {
        float dl[4];
        #pragma unroll
        for (int u = 0; u < 4; u++) dl[u] = fmaxf(g_n[0][b*L_ + ti + row + u], EPSF);
        #pragma unroll
        for (int q = 0; q < 4; q++) {
            int col = cg2 + 32*q;
            float drx = fmaxf(g_n[1][b*L_ + col  ], EPSF);  // clip each norm (ref)
            float dry = fmaxf(g_n[1][b*L_ + col+1], EPSF);
            #pragma unroll
            for (int u = 0; u < 4; u++) {
                float lo, hi; UNPK2(lo, hi, acc[u][q]);
                lo /= (dl[u] * drx);
                hi /= (dl[u] * dry);
                *(float2*)(Sout + (size_t)(ti + row + u) * L_ + col) = make_float2(lo, hi);
            }
        }
    }
}

// ---------------- masked max/mean reductions over S (coalesced both axes) ----------------
// grid (NCH, B), 256 thr: warps 0-3 = row reductions, warps 4-7 = thread-per-column
__global__ __launch_bounds__(256) void k_reduce(
    const float* __restrict__ m1, const float* __restrict__ m2,
    float* __restrict__ out)
{
    int p = blockIdx.x, b = blockIdx.y;
    const float* Sp = g_S + ((size_t)(b*NCH + p)) * L_ * L_;
    __shared__ float mA[L_], mB2[L_];
    int tid = threadIdx.x;
    if (tid < 128) mA[tid] = m1[b*L_ + tid];
    else           mB2[tid-128] = m2[b*L_ + tid - 128];
    __syncthreads();
    int w = tid >> 5, lane = tid & 31;
    if (w < 4) {
        float cnt = fmaxf((float)g_len[1][b], EPSF);
        for (int r = 0; r < 32; r++) {
            int i = (w << 5) + r;
            float mx = NEGINF, sm = 0.f;
            #pragma unroll
            for (int kk = 0; kk < 4; kk++) {
                int j = lane + (kk << 5);
                float v = Sp[(size_t)i * L_ + j];
                if (mB2[j] != 0.f) { mx = fmaxf(mx, v); sm += v; }
            }
            #pragma unroll
            for (int o = 16; o; o >>= 1) {
                mx = fmaxf(mx, __shfl_xor_sync(0xffffffffu, mx, o));
                sm += __shfl_xor_sync(0xffffffffu, sm, o);
            }
            if (lane == 0) {
                float* o_ = out + ((size_t)(b*2 + 0)*L_ + i) * OUTD;
                float mean = sm / cnt;
                if (p == P_) { o_[0] = mx; o_[1] = mean; }
                else         { o_[36 + p] = mx; o_[52 + p] = mean; }
            }
        }
    } else {
        int t = ((w - 4) << 5) + lane;
        float cnt = fmaxf((float)g_len[0][b], EPSF);
        float mx = NEGINF, sm = 0.f;
        for (int u = 0; u < L_; u += 4) {
            #pragma unroll
            for (int x = 0; x < 4; x++) {
                float v = Sp[(size_t)(u + x) * L_ + t];
                if (mA[u + x] != 0.f) { mx = fmaxf(mx, v); sm += v; }
            }
        }
        float* o_ = out + ((size_t)(b*2 + 1)*L_ + t) * OUTD;
        float mean = sm / cnt;
        if (p == P_) { o_[0] = mx; o_[1] = mean; }
        else         { o_[36 + p] = mx; o_[52 + p] = mean; }
    }
}

// ---------------- attention sums/maxes + fused softmax ----------------
// grid (L/TT, B, 2)
__global__ __launch_bounds__(256) void k_att(
    const float* __restrict__ m1, const float* __restrict__ m2)
{
    int tb = blockIdx.x, b = blockIdx.y, s = blockIdx.z;
    int other = 1 - s;
    int lenO = g_len[other][b];
    const float* C = g_c[other] + (size_t)b * L_ * H_;
    const float* Scos = g_S + ((size_t)(b*NCH + P_)) * L_ * L_;
    const float* mkS = s ? m2 : m1;
    __shared__ float cw[TT][L_];
    __shared__ float red[8];
    int tid = threadIdx.x;
    for (int idx = tid; idx < TT*L_; idx += 256) {
        int tt = idx >> 7, u = idx & (L_-1);
        int t = tb*TT + tt;
        cw[tt][u] = (s == 0) ? Scos[(size_t)t * L_ + u] : Scos[(size_t)u * L_ + t];
    }
    __syncthreads();

    float sm[TT][3], mx[TT][3];
    #pragma unroll
    for (int tt = 0; tt < TT; tt++)
        #pragma unroll
        for (int q = 0; q < 3; q++) { sm[tt][q] = 0.f; mx[tt][q] = NEGINF; }

    for (int u = 0; u < lenO; u++) {
        float c0 = C[(size_t)u*H_ + tid];
        float c1 = C[(size_t)u*H_ + tid + 256];
        float c2 = C[(size_t)u*H_ + tid + 512];
        #pragma unroll
        for (int tt = 0; tt < TT; tt++) {
            float wv = cw[tt][u];
            float p0 = wv * c0, p1 = wv * c1, p2 = wv * c2;
            sm[tt][0] += p0; sm[tt][1] += p1; sm[tt][2] += p2;
            mx[tt][0] = fmaxf(mx[tt][0], p0);
            mx[tt][1] = fmaxf(mx[tt][1], p1);
            mx[tt][2] = fmaxf(mx[tt][2], p2);
        }
    }

    int w = tid >> 5, lane = tid & 31;
    #pragma unroll
    for (int tt = 0; tt < TT; tt++) {
        int t = tb*TT + tt;
        size_t base = ((size_t)(b*L_ + t)) * H_;
        g_attM[s][base + tid]       = mx[tt][0];
        g_attM[s][base + tid + 256] = mx[tt][1];
        g_attM[s][base + tid + 512] = mx[tt][2];
    }

    // fused masked softmax over H (block holds the full 768-row per token)
    #pragma unroll
    for (int tt = 0; tt < TT; tt++) {
        int t = tb*TT + tt;
        size_t base = ((size_t)(b*L_ + t)) * H_;
        float m = mkS[b*L_ + t];           // uniform across block
        if (m == 0.f) {
            g_attS[s][base + tid]       = 1.f / (float)H_;
            g_attS[s][base + tid + 256] = 1.f / (float)H_;
            g_attS[s][base + tid + 512] = 1.f / (float)H_;
            continue;
        }
        float lm = fmaxf(fmaxf(sm[tt][0], sm[tt][1]), sm[tt][2]);
        #pragma unroll
        for (int o = 16; o; o >>= 1) lm = fmaxf(lm, __shfl_xor_sync(0xffffffffu, lm, o));
        if (lane == 0) red[w] = lm;
        __syncthreads();
        float bm = red[0];
        #pragma unroll
        for (int i = 1; i < 8; i++) bm = fmaxf(bm, red[i]);
        __syncthreads();
        float e0 = expf(sm[tt][0] - bm), e1 = expf(sm[tt][1] - bm), e2 = expf(sm[tt][2] - bm);
        float ls = e0 + e1 + e2;
        #pragma unroll
        for (int o = 16; o; o >>= 1) ls += __shfl_xor_sync(0xffffffffu, ls, o);
        if (lane == 0) red[w] = ls;
        __syncthreads();
        float bs = red[0]+red[1]+red[2]+red[3]+red[4]+red[5]+red[6]+red[7];
        __syncthreads();
        float inv = 1.f / bs;
        g_attS[s][base + tid]       = e0 * inv;
        g_attS[s][base + tid + 256] = e1 * inv;
        g_attS[s][base + tid + 512] = e2 * inv;
    }
}

// ---------------- per-token weighted cosines (packed f32x2) ----------------
__global__ __launch_bounds__(256) void k_final(
    const float* __restrict__ wff, const float* __restrict__ wfb,
    const float* __restrict__ watt, const float* __restrict__ wmatt,
    float* __restrict__ out)
{
    int t = blockIdx.x, b = blockIdx.y, s = blockIdx.z;
    int other = 1 - s;
    __shared__ __align__(16) float sa[H_];
    __shared__ __align__(16) float sv[4][H_];
    int tid = threadIdx.x;
    const float* a = g_c[s] + ((size_t)(b*L_ + t)) * H_;
    int lenO = g_len[other][b];
    int lp = lenO > 0 ? lenO - 1 : 0;
    const float* v_ff  = g_c[other] + ((size_t)(b*L_ + lp)) * H_;
    const float* v_bf  = g_c[other] + ((size_t)(b*L_)) * H_;
    const float* v_am  = g_attS[s] + ((size_t)(b*L_ + t)) * H_;
    const float* v_amx = g_attM[s] + ((size_t)(b*L_ + t)) * H_;
    for (int h = tid; h < H_; h += 256) {
        sa[h] = a[h];
        sv[0][h] = v_ff[h];
        sv[1][h] = v_bf[h];
        sv[2][h] = v_am[h];
        sv[3][h] = v_amx[h];
    }
    __syncthreads();

    unsigned int sa_b = (unsigned int)__cvta_generic_to_shared(sa);
    unsigned int sv_b = (unsigned int)__cvta_generic_to_shared(&sv[0][0]);
    int w = tid >> 5, lane = tid & 31;
    float* o_ = out + ((size_t)(b*2 + s)*L_ + t) * OUTD;
    for (int task = w; task < 68; task += 8) {
        int q = task / 17;
        int tt = task - q * 17;
        const float* W = (q == 0) ? wff : (q == 1) ? wfb : (q == 2) ? watt : wmatt;
        int base = (q == 0) ? 2 : (q == 1) ? 19 : (q == 2) ? 68 : 85;
        const float* Wr = W + tt * H_;
        unsigned int svq = sv_b + (unsigned int)(q * H_ * 4);
        ull sav = 0ull, saa = 0ull, svv = 0ull;
        if (tt < P_) {
            #pragma unroll
            for (int k = 0; k < 12; k++) {
                int h2 = (lane + (k << 5)) << 1;   // float index of pair
                ull a2 = lds64(sa_b + (unsigned int)(h2 << 2));
                ull v2 = lds64(svq  + (unsigned int)(h2 << 2));
                ull w2 = ldg64(Wr + h2);
                MUL2(a2, a2, w2);
                MUL2(v2, v2, w2);
                FMA2(sav, a2, v2);
                FMA2(saa, a2, a2);
                FMA2(svv, v2, v2);
            }
        } else {
            #pragma unroll
            for (int k = 0; k < 12; k++) {
                int h2 = (lane + (k << 5)) << 1;
                ull a2 = lds64(sa_b + (unsigned int)(h2 << 2));
                ull v2 = lds64(svq  + (unsigned int)(h2 << 2));
                FMA2(sav, a2, v2);
                FMA2(saa, a2, a2);
                FMA2(svv, v2, v2);
            }
        }
        float lo, hi, fsav, fsaa, fsvv;
        UNPK2(lo, hi, sav); fsav = lo + hi;
        UNPK2(lo, hi, saa); fsaa = lo + hi;
        UNPK2(lo, hi, svv); fsvv = lo + hi;
        #pragma unroll
        for (int o = 16; o; o >>= 1) {
            fsav += __shfl_xor_sync(0xffffffffu, fsav, o);
            fsaa += __shfl_xor_sync(0xffffffffu, fsaa, o);
            fsvv += __shfl_xor_sync(0xffffffffu, fsvv, o);
        }
        if (lane == 0) {
            float na = fmaxf(sqrtf(fsaa), EPSF);
            float nv = fmaxf(sqrtf(fsvv), EPSF);
            int col = (tt == P_) ? base : (base + 1 + tt);
            o_[col] = fsav / (na * nv);
        }
    }
}

// ---------------- launch ----------------
extern "C" void kernel_launch(void* const* d_in, const int* in_sizes, int n_in,
                              void* d_out, int out_size) {
    const float* c1    = (const float*)d_in[0];
    const float* m1    = (const float*)d_in[1];
    const float* c2    = (const float*)d_in[2];
    const float* m2    = (const float*)d_in[3];
    const float* wff   = (const float*)d_in[4];
    const float* wfb   = (const float*)d_in[5];
    const float* wmp   = (const float*)d_in[6];
    const float* watt  = (const float*)d_in[7];
    const float* wmatt = (const float*)d_in[8];
    float* out = (float*)d_out;
    (void)in_sizes; (void)n_in; (void)out_size;

    k_len    <<<1, 64>>>(m1, m2);
    k_prep   <<<dim3(L_, B_, 2), 256>>>(c1, m1, c2, m2, wmp);
    k_gemm   <<<dim3(2, NCH, B_), 256>>>(wmp);
    k_reduce <<<dim3(NCH, B_), 256>>>(m1, m2, out);
    k_att    <<<dim3(L_/TT, B_, 2), 256>>>(m1, m2);
    k_final  <<<dim3(L_, B_, 2), 256>>>(wff, wfb, watt, wmatt, out);
}

// round 8
// speedup vs baseline: 1.0748x; 1.0681x over previous
#include <cuda_runtime.h>
#include <math.h>

typedef unsigned long long ull;

// Problem constants (fixed by reference setup_inputs)
#define B_  8
#define L_  128
#define H_  768
#define P_  16
#define NCH 17          // 16 perspectives + plain cosine channel
#define OUTD 102
#define EPSF 1e-8f
#define NEGINF (-1e30f)
#define TT 16           // token tile for attention kernel

// ---------------- scratch (static device memory; no allocation) ----------------
__device__ float g_c[2][B_*L_*H_];      // masked contexts
__device__ float g_n[2][B_*L_];         // plain L2 norms
__device__ float g_nw[2][B_*L_*P_];     // w_mp-weighted norms
__device__ float g_Scos[B_*L_*L_];      // cosine channel only (for k_att)
__device__ float g_attS[2][B_*L_*H_];   // att softmax (att_mean)
__device__ float g_attM[2][B_*L_*H_];   // att maxes
__device__ int   g_len[2][B_];

// ---------------- packed fp32x2 helpers ----------------
#define FMA2(d,a,b)    asm("fma.rn.f32x2 %0, %1, %2, %0;" : "+l"(d) : "l"(a), "l"(b))
#define MUL2(d,a,b)    asm("mul.rn.f32x2 %0, %1, %2;" : "=l"(d) : "l"(a), "l"(b))
#define PACK2(d,x)     asm("mov.b64 %0, {%1, %2};" : "=l"(d) : "f"(x), "f"(x))
#define UNPK2(lo,hi,v) asm("mov.b64 {%0, %1}, %2;" : "=f"(lo), "=f"(hi) : "l"(v))

__device__ __forceinline__ ull lds64(unsigned int addr) {
    ull v; asm volatile("ld.shared.b64 %0, [%1];" : "=l"(v) : "r"(addr)); return v;
}
__device__ __forceinline__ ull ldg64(const float* p) {
    ull v; asm volatile("ld.global.nc.b64 %0, [%1];" : "=l"(v) : "l"(p)); return v;
}

// ---------------- lengths ----------------
__global__ void k_len(const float* __restrict__ m1, const float* __restrict__ m2) {
    int t = threadIdx.x;
    if (t < 16) {
        int s = t >> 3, b = t & 7;
        const float* mk = s ? m2 : m1;
        float acc = 0.f;
        for (int j = 0; j < L_; j++) acc += mk[b*L_ + j];
        g_len[s][b] = (int)(acc + 0.5f);
    }
}

// ---------------- masked context + norms ----------------
__global__ __launch_bounds__(256) void k_prep(
    const float* __restrict__ ctx1, const float* __restrict__ m1,
    const float* __restrict__ ctx2, const float* __restrict__ m2,
    const float* __restrict__ w_mp)
{
    int i = blockIdx.x, b = blockIdx.y, s = blockIdx.z;
    const float* ctx = s ? ctx2 : ctx1;
    const float* mk  = s ? m2   : m1;
    __shared__ float cs[H_];
    float m = mk[b*L_ + i];
    int tid = threadIdx.x;
    float* cdst = g_c[s] + (size_t)(b*L_ + i) * H_;
    const float* csrc = ctx + (size_t)(b*L_ + i) * H_;
    for (int h = tid; h < H_; h += 256) {
        float v = csrc[h] * m;
        cs[h] = v;
        cdst[h] = v;
    }
    __syncthreads();
    int w = tid >> 5, lane = tid & 31;
    for (int t = w; t < NCH; t += 8) {
        float acc = 0.f;
        #pragma unroll
        for (int k = 0; k < H_/32; k++) {
            int h = lane + 32*k;
            float c = cs[h];
            float x = (t < P_) ? w_mp[t*H_ + h] * c : c;
            acc = fmaf(x, x, acc);
        }
        #pragma unroll
        for (int o = 16; o; o >>= 1) acc += __shfl_xor_sync(0xffffffffu, acc, o);
        if (lane == 0) {
            if (t == P_) g_n[s][b*L_ + i] = sqrtf(acc);
            else         g_nw[s][(b*L_ + i)*P_ + t] = sqrtf(acc);
        }
    }
}

// ---------------- 17-channel pairwise GEMM fused with masked reductions ----------------
// grid (NCH, B): one 128x128 tile per block, 8x8 per-thread micro-tile, f32x2 FMA.
// Epilogue computes masked row/col max+mean in-block -> writes stats to out.
// Only the cosine channel tile is stored (g_Scos) for k_att.
__global__ __launch_bounds__(256) void k_gemm(
    const float* __restrict__ w_mp,
    const float* __restrict__ m1, const float* __restrict__ m2,
    float* __restrict__ out)
{
    int p = blockIdx.x, b = blockIdx.y;
    const float* A  = g_c[0] + (size_t)b * L_ * H_;
    const float* Bm = g_c[1] + (size_t)b * L_ * H_;
    __shared__ __align__(16) float As[16][128];
    __shared__ __align__(16) float Bs[16][128];
    __shared__ float mA[L_], mB[L_];
    __shared__ float red[16][132];     // padded pitch to dodge bank conflicts
    int tid = threadIdx.x;
    if (tid < 128) mA[tid] = m1[b*L_ + tid];
    else           mB[tid-128] = m2[b*L_ + tid - 128];

    int lr = tid & 127, lk = (tid >> 7) << 3;   // loader: row 0..127, koff {0,8}
    int tr = tid >> 4,  tc = tid & 15;          // compute: 8 rows (tr*8+), 8 cols (tc*2+32q+e)
    const bool wt = (p < P_);
    const float* wp = w_mp + p * H_;

    ull acc[8][4];
    #pragma unroll
    for (int r = 0; r < 8; r++)
        #pragma unroll
        for (int q = 0; q < 4; q++) acc[r][q] = 0ull;

    unsigned int bs_b = (unsigned int)__cvta_generic_to_shared(&Bs[0][0]);

    // prefetch chunk 0
    float4 pa0, pa1, pb0, pb1;
    {
        const float* Ap = A  + (size_t)lr * H_ + lk;
        const float* Bp = Bm + (size_t)lr * H_ + lk;
        pa0 = *(const float4*)(Ap);     pa1 = *(const float4*)(Ap + 4);
        pb0 = *(const float4*)(Bp);     pb1 = *(const float4*)(Bp + 4);
        if (wt) {
            float4 w0 = *(const float4*)(wp + lk);
            float4 w1 = *(const float4*)(wp + lk + 4);
            pa0.x*=w0.x; pa0.y*=w0.y; pa0.z*=w0.z; pa0.w*=w0.w;
            pa1.x*=w1.x; pa1.y*=w1.y; pa1.z*=w1.z; pa1.w*=w1.w;
            pb0.x*=w0.x; pb0.y*=w0.y; pb0.z*=w0.z; pb0.w*=w0.w;
            pb1.x*=w1.x; pb1.y*=w1.y; pb1.z*=w1.z; pb1.w*=w1.w;
        }
    }

    for (int c = 0; c < H_/16; c++) {
        As[lk+0][lr]=pa0.x; As[lk+1][lr]=pa0.y; As[lk+2][lr]=pa0.z; As[lk+3][lr]=pa0.w;
        As[lk+4][lr]=pa1.x; As[lk+5][lr]=pa1.y; As[lk+6][lr]=pa1.z; As[lk+7][lr]=pa1.w;
        Bs[lk+0][lr]=pb0.x; Bs[lk+1][lr]=pb0.y; Bs[lk+2][lr]=pb0.z; Bs[lk+3][lr]=pb0.w;
        Bs[lk+4][lr]=pb1.x; Bs[lk+5][lr]=pb1.y; Bs[lk+6][lr]=pb1.z; Bs[lk+7][lr]=pb1.w;
        __syncthreads();
        if (c + 1 < H_/16) {
            int k0 = (c + 1) * 16;
            const float* Ap = A  + (size_t)lr * H_ + k0 + lk;
            const float* Bp = Bm + (size_t)lr * H_ + k0 + lk;
            pa0 = *(const float4*)(Ap);     pa1 = *(const float4*)(Ap + 4);
            pb0 = *(const float4*)(Bp);     pb1 = *(const float4*)(Bp + 4);
            if (wt) {
                float4 w0 = *(const float4*)(wp + k0 + lk);
                float4 w1 = *(const float4*)(wp + k0 + lk + 4);
                pa0.x*=w0.x; pa0.y*=w0.y; pa0.z*=w0.z; pa0.w*=w0.w;
                pa1.x*=w1.x; pa1.y*=w1.y; pa1.z*=w1.z; pa1.w*=w1.w;
                pb0.x*=w0.x; pb0.y*=w0.y; pb0.z*=w0.z; pb0.w*=w0.w;
                pb1.x*=w1.x; pb1.y*=w1.y; pb1.z*=w1.z; pb1.w*=w1.w;
            }
        }
        #pragma unroll
        for (int k = 0; k < 16; k++) {
            float4 ra0 = *(const float4*)&As[k][tr << 3];
            float4 ra1 = *(const float4*)&As[k][(tr << 3) + 4];
            unsigned int bb = bs_b + (unsigned int)((((k << 7) + (tc << 1))) << 2);
            ull b0 = lds64(bb);
            ull b1 = lds64(bb + 32*4);
            ull b2 = lds64(bb + 64*4);
            ull b3 = lds64(bb + 96*4);
            float av[8] = {ra0.x, ra0.y, ra0.z, ra0.w, ra1.x, ra1.y, ra1.z, ra1.w};
            #pragma unroll
            for (int r = 0; r < 8; r++) {
                ull aa; PACK2(aa, av[r]);
                FMA2(acc[r][0], aa, b0);
                FMA2(acc[r][1], aa, b1);
                FMA2(acc[r][2], aa, b2);
                FMA2(acc[r][3], aa, b3);
            }
        }
        __syncthreads();
    }

    // ------- epilogue: normalize in registers -------
    float val[8][8];   // [row r][col-slot cc], col = tc*2 + 32*(cc>>1) + (cc&1)
    #pragma unroll
    for (int r = 0; r < 8; r++)
        #pragma unroll
        for (int q = 0; q < 4; q++)
            UNPK2(val[r][2*q], val[r][2*q+1], acc[r][q]);

    if (wt) {
        float dl[8], dr[8];
        #pragma unroll
        for (int r = 0; r < 8; r++) dl[r] = g_nw[0][(b*L_ + (tr*8 + r))*P_ + p];
        #pragma unroll
        for (int q = 0; q < 4; q++) {
            dr[2*q]   = g_nw[1][(b*L_ + tc*2 + 32*q    )*P_ + p];
            dr[2*q+1] = g_nw[1][(b*L_ + tc*2 + 32*q + 1)*P_ + p];
        }
        #pragma unroll
        for (int r = 0; r < 8; r++)
            #pragma unroll
            for (int cc = 0; cc < 8; cc++)
                val[r][cc] /= fmaxf(dl[r] * dr[cc], EPSF);      // clip PRODUCT (ref)
    } else {
        float dl[8], dr[8];
        #pragma unroll
        for (int r = 0; r < 8; r++) dl[r] = fmaxf(g_n[0][b*L_ + tr*8 + r], EPSF);
        #pragma unroll
        for (int q = 0; q < 4; q++) {
            dr[2*q]   = fmaxf(g_n[1][b*L_ + tc*2 + 32*q    ], EPSF);  // clip each (ref)
            dr[2*q+1] = fmaxf(g_n[1][b*L_ + tc*2 + 32*q + 1], EPSF);
        }
        #pragma unroll
        for (int r = 0; r < 8; r++)
            #pragma unroll
            for (int cc = 0; cc < 8; cc++)
                val[r][cc] /= (dl[r] * dr[cc]);
    }

    // masks into registers
    float rm[8], cmk[8];
    #pragma unroll
    for (int r = 0; r < 8; r++) rm[r] = mA[tr*8 + r];
    #pragma unroll
    for (int q = 0; q < 4; q++) {
        cmk[2*q]   = mB[tc*2 + 32*q];
        cmk[2*q+1] = mB[tc*2 + 32*q + 1];
    }
    float cnt2 = fmaxf((float)g_len[1][b], EPSF);
    float cnt1 = fmaxf((float)g_len[0][b], EPSF);

    // cosine channel: store tile for k_att
    if (!wt) {
        #pragma unroll
        for (int r = 0; r < 8; r++) {
            float* dst = g_Scos + ((size_t)(b*L_ + tr*8 + r)) * L_;
            #pragma unroll
            for (int q = 0; q < 4; q++)
                *(float2*)(dst + tc*2 + 32*q) = make_float2(val[r][2*q], val[r][2*q+1]);
        }
    }

    // ------- row reductions (over j, mask_2) : 16-lane shuffle -------
    #pragma unroll
    for (int r = 0; r < 8; r++) {
        float mx = NEGINF, sm = 0.f;
        #pragma unroll
        for (int cc = 0; cc < 8; cc++)
            if (cmk[cc] != 0.f) { mx = fmaxf(mx, val[r][cc]); sm += val[r][cc]; }
        #pragma unroll
        for (int o = 8; o; o >>= 1) {
            mx = fmaxf(mx, __shfl_xor_sync(0xffffffffu, mx, o));
            sm += __shfl_xor_sync(0xffffffffu, sm, o);
        }
        if (tc == 0) {
            int i = tr*8 + r;
            float* o_ = out + ((size_t)(b*2 + 0)*L_ + i) * OUTD;
            float mean = sm / cnt2;
            if (!wt) { o_[0] = mx; o_[1] = mean; }
            else     { o_[36 + p] = mx; o_[52 + p] = mean; }
        }
    }

    // ------- col reductions (over i, mask_1) : smem stage -------
    float cmx[8], csm[8];
    #pragma unroll
    for (int cc = 0; cc < 8; cc++) { cmx[cc] = NEGINF; csm[cc] = 0.f; }
    #pragma unroll
    for (int r = 0; r < 8; r++)
        if (rm[r] != 0.f)
            #pragma unroll
            for (int cc = 0; cc < 8; cc++) {
                cmx[cc] = fmaxf(cmx[cc], val[r][cc]);
                csm[cc] += val[r][cc];
            }

    #pragma unroll
    for (int q = 0; q < 4; q++) {
        red[tr][tc*2 + 32*q]     = cmx[2*q];
        red[tr][tc*2 + 32*q + 1] = cmx[2*q+1];
    }
    __syncthreads();
    float fmx = NEGINF;
    if (tid < 128) {
        fmx = red[0][tid];
        #pragma unroll
        for (int t = 1; t < 16; t++) fmx = fmaxf(fmx, red[t][tid]);
    }
    __syncthreads();
    #pragma unroll
    for (int q = 0; q < 4; q++) {
        red[tr][tc*2 + 32*q]     = csm[2*q];
        red[tr][tc*2 + 32*q + 1] = csm[2*q+1];
    }
    __syncthreads();
    if (tid < 128) {
        float fsm = 0.f;
        #pragma unroll
        for (int t = 0; t < 16; t++) fsm += red[t][tid];
        float* o_ = out + ((size_t)(b*2 + 1)*L_ + tid) * OUTD;
        float mean = fsm / cnt1;
        if (!wt) { o_[0] = fmx; o_[1] = mean; }
        else     { o_[36 + p] = fmx; o_[52 + p] = mean; }
    }
}

// ---------------- attention sums/maxes + fused softmax ----------------
// grid (L/TT, B, 2)
__global__ __launch_bounds__(256) void k_att(
    const float* __restrict__ m1, const float* __restrict__ m2)
{
    int tb = blockIdx.x, b = blockIdx.y, s = blockIdx.z;
    int other = 1 - s;
    int lenO = g_len[other][b];
    const float* C = g_c[other] + (size_t)b * L_ * H_;
    const float* Scos = g_Scos + (size_t)b * L_ * L_;
    const float* mkS = s ? m2 : m1;
    __shared__ float cw[TT][L_];
    __shared__ float red[8];
    int tid = threadIdx.x;
    for (int idx = tid; idx < TT*L_; idx += 256) {
        int tt = idx >> 7, u = idx & (L_-1);
        int t = tb*TT + tt;
        cw[tt][u] = (s == 0) ? Scos[(size_t)t * L_ + u] : Scos[(size_t)u * L_ + t];
    }
    __syncthreads();

    float sm[TT][3], mx[TT][3];
    #pragma unroll
    for (int tt = 0; tt < TT; tt++)
        #pragma unroll
        for (int q = 0; q < 3; q++) { sm[tt][q] = 0.f; mx[tt][q] = NEGINF; }

    for (int u = 0; u < lenO; u++) {
        float c0 = C[(size_t)u*H_ + tid];
        float c1 = C[(size_t)u*H_ + tid + 256];
        float c2 = C[(size_t)u*H_ + tid + 512];
        #pragma unroll
        for (int tt = 0; tt < TT; tt++) {
            float wv = cw[tt][u];
            float p0 = wv * c0, p1 = wv * c1, p2 = wv * c2;
            sm[tt][0] += p0; sm[tt][1] += p1; sm[tt][2] += p2;
            mx[tt][0] = fmaxf(mx[tt][0], p0);
            mx[tt][1] = fmaxf(mx[tt][1], p1);
            mx[tt][2] = fmaxf(mx[tt][2], p2);
        }
    }

    int w = tid >> 5, lane = tid & 31;
    #pragma unroll
    for (int tt = 0; tt < TT; tt++) {
        int t = tb*TT + tt;
        size_t base = ((size_t)(b*L_ + t)) * H_;
        g_attM[s][base + tid]       = mx[tt][0];
        g_attM[s][base + tid + 256] = mx[tt][1];
        g_attM[s][base + tid + 512] = mx[tt][2];
    }

    // fused masked softmax over H
    #pragma unroll
    for (int tt = 0; tt < TT; tt++) {
        int t = tb*TT + tt;
        size_t base = ((size_t)(b*L_ + t)) * H_;
        float m = mkS[b*L_ + t];
        if (m == 0.f) {
            g_attS[s][base + tid]       = 1.f / (float)H_;
            g_attS[s][base + tid + 256] = 1.f / (float)H_;
            g_attS[s][base + tid + 512] = 1.f / (float)H_;
            continue;
        }
        float lm = fmaxf(fmaxf(sm[tt][0], sm[tt][1]), sm[tt][2]);
        #pragma unroll
        for (int o = 16; o; o >>= 1) lm = fmaxf(lm, __shfl_xor_sync(0xffffffffu, lm, o));
        if (lane == 0) red[w] = lm;
        __syncthreads();
        float bm = red[0];
        #pragma unroll
        for (int i = 1; i < 8; i++) bm = fmaxf(bm, red[i]);
        __syncthreads();
        float e0 = expf(sm[tt][0] - bm), e1 = expf(sm[tt][1] - bm), e2 = expf(sm[tt][2] - bm);
        float ls = e0 + e1 + e2;
        #pragma unroll
        for (int o = 16; o; o >>= 1) ls += __shfl_xor_sync(0xffffffffu, ls, o);
        if (lane == 0) red[w] = ls;
        __syncthreads();
        float bs = red[0]+red[1]+red[2]+red[3]+red[4]+red[5]+red[6]+red[7];
        __syncthreads();
        float inv = 1.f / bs;
        g_attS[s][base + tid]       = e0 * inv;
        g_attS[s][base + tid + 256] = e1 * inv;
        g_attS[s][base + tid + 512] = e2 * inv;
    }
}

// ---------------- per-token weighted cosines (packed f32x2) ----------------
__global__ __launch_bounds__(256) void k_final(
    const float* __restrict__ wff, const float* __restrict__ wfb,
    const float* __restrict__ watt, const float* __restrict__ wmatt,
    float* __restrict__ out)
{
    int t = blockIdx.x, b = blockIdx.y, s = blockIdx.z;
    int other = 1 - s;
    __shared__ __align__(16) float sa[H_];
    __shared__ __align__(16) float sv[4][H_];
    int tid = threadIdx.x;
    const float* a = g_c[s] + ((size_t)(b*L_ + t)) * H_;
    int lenO = g_len[other][b];
    int lp = lenO > 0 ? lenO - 1 : 0;
    const float* v_ff  = g_c[other] + ((size_t)(b*L_ + lp)) * H_;
    const float* v_bf  = g_c[other] + ((size_t)(b*L_)) * H_;
    const float* v_am  = g_attS[s] + ((size_t)(b*L_ + t)) * H_;
    const float* v_amx = g_attM[s] + ((size_t)(b*L_ + t)) * H_;
    for (int h = tid; h < H_; h += 256) {
        sa[h] = a[h];
        sv[0][h] = v_ff[h];
        sv[1][h] = v_bf[h];
        sv[2][h] = v_am[h];
        sv[3][h] = v_amx[h];
    }
    __syncthreads();

    unsigned int sa_b = (unsigned int)__cvta_generic_to_shared(sa);
    unsigned int sv_b = (unsigned int)__cvta_generic_to_shared(&sv[0][0]);
    int w = tid >> 5, lane = tid & 31;
    float* o_ = out + ((size_t)(b*2 + s)*L_ + t) * OUTD;
    for (int task = w; task < 68; task += 8) {
        int q = task / 17;
        int tt = task - q * 17;
        const float* W = (q == 0) ? wff : (q == 1) ? wfb : (q == 2) ? watt : wmatt;
        int base = (q == 0) ? 2 : (q == 1) ? 19 : (q == 2) ? 68 : 85;
        const float* Wr = W + tt * H_;
        unsigned int svq = sv_b + (unsigned int)(q * H_ * 4);
        ull sav = 0ull, saa = 0ull, svv = 0ull;
        if (tt < P_) {
            #pragma unroll
            for (int k = 0; k < 12; k++) {
                int h2 = (lane + (k << 5)) << 1;
                ull a2 = lds64(sa_b + (unsigned int)(h2 << 2));
                ull v2 = lds64(svq  + (unsigned int)(h2 << 2));
                ull w2 = ldg64(Wr + h2);
                MUL2(a2, a2, w2);
                MUL2(v2, v2, w2);
                FMA2(sav, a2, v2);
                FMA2(saa, a2, a2);
                FMA2(svv, v2, v2);
            }
        } else {
            #pragma unroll
            for (int k = 0; k < 12; k++) {
                int h2 = (lane + (k << 5)) << 1;
                ull a2 = lds64(sa_b + (unsigned int)(h2 << 2));
                ull v2 = lds64(svq  + (unsigned int)(h2 << 2));
                FMA2(sav, a2, v2);
                FMA2(saa, a2, a2);
                FMA2(svv, v2, v2);
            }
        }
        float lo, hi, fsav, fsaa, fsvv;
        UNPK2(lo, hi, sav); fsav = lo + hi;
        UNPK2(lo, hi, saa); fsaa = lo + hi;
        UNPK2(lo, hi, svv); fsvv = lo + hi;
        #pragma unroll
        for (int o = 16; o; o >>= 1) {
            fsav += __shfl_xor_sync(0xffffffffu, fsav, o);
            fsaa += __shfl_xor_sync(0xffffffffu, fsaa, o);
            fsvv += __shfl_xor_sync(0xffffffffu, fsvv, o);
        }
        if (lane == 0) {
            float na = fmaxf(sqrtf(fsaa), EPSF);
            float nv = fmaxf(sqrtf(fsvv), EPSF);
            int col = (tt == P_) ? base : (base + 1 + tt);
            o_[col] = fsav / (na * nv);
        }
    }
}

// ---------------- launch ----------------
extern "C" void kernel_launch(void* const* d_in, const int* in_sizes, int n_in,
                              void* d_out, int out_size) {
    const float* c1    = (const float*)d_in[0];
    const float* m1    = (const float*)d_in[1];
    const float* c2    = (const float*)d_in[2];
    const float* m2    = (const float*)d_in[3];
    const float* wff   = (const float*)d_in[4];
    const float* wfb   = (const float*)d_in[5];
    const float* wmp   = (const float*)d_in[6];
    const float* watt  = (const float*)d_in[7];
    const float* wmatt = (const float*)d_in[8];
    float* out = (float*)d_out;
    (void)in_sizes; (void)n_in; (void)out_size;

    k_len    <<<1, 64>>>(m1, m2);
    k_prep   <<<dim3(L_, B_, 2), 256>>>(c1, m1, c2, m2, wmp);
    k_gemm   <<<dim3(NCH, B_), 256>>>(wmp, m1, m2, out);
    k_att    <<<dim3(L_/TT, B_, 2), 256>>>(m1, m2);
    k_final  <<<dim3(L_, B_, 2), 256>>>(wff, wfb, watt, wmatt, out);
}

// round 9
// speedup vs baseline: 1.1865x; 1.1039x over previous
#include <cuda_runtime.h>
#include <math.h>

typedef unsigned long long ull;

// Problem constants (fixed by reference setup_inputs)
#define B_  8
#define L_  128
#define H_  768
#define P_  16
#define NCH 17          // 16 perspectives + plain cosine channel
#define OUTD 102
#define EPSF 1e-8f
#define NEGINF (-1e30f)
#define TT 16           // token tile for attention kernel
#define ATT_THR 384     // 384 threads = 768 h / 2 packed
#define ATT_W   12      // warps per att block

// ---------------- scratch (static device memory; no allocation) ----------------
__device__ float g_c[2][B_*L_*H_];      // masked contexts
__device__ float g_n[2][B_*L_];         // plain L2 norms
__device__ float g_nw[2][B_*L_*P_];     // w_mp-weighted norms
__device__ float g_Scos[B_*L_*L_];      // cosine channel only (for k_att)
__device__ float g_attS[2][B_*L_*H_];   // att softmax (att_mean)
__device__ float g_attM[2][B_*L_*H_];   // att maxes
__device__ int   g_len[2][B_];

// ---------------- packed fp32x2 helpers ----------------
#define FMA2(d,a,b)    asm("fma.rn.f32x2 %0, %1, %2, %0;" : "+l"(d) : "l"(a), "l"(b))
#define MUL2(d,a,b)    asm("mul.rn.f32x2 %0, %1, %2;" : "=l"(d) : "l"(a), "l"(b))
#define PACK2(d,x)     asm("mov.b64 %0, {%1, %2};" : "=l"(d) : "f"(x), "f"(x))
#define UNPK2(lo,hi,v) asm("mov.b64 {%0, %1}, %2;" : "=f"(lo), "=f"(hi) : "l"(v))

__device__ __forceinline__ ull lds64(unsigned int addr) {
    ull v; asm volatile("ld.shared.b64 %0, [%1];" : "=l"(v) : "r"(addr)); return v;
}
__device__ __forceinline__ ull ldg64(const float* p) {
    ull v; asm volatile("ld.global.nc.b64 %0, [%1];" : "=l"(v) : "l"(p)); return v;
}

// ---------------- lengths ----------------
__global__ void k_len(const float* __restrict__ m1, const float* __restrict__ m2) {
    int t = threadIdx.x;
    if (t < 16) {
        int s = t >> 3, b = t & 7;
        const float* mk = s ? m2 : m1;
        float acc = 0.f;
        for (int j = 0; j < L_; j++) acc += mk[b*L_ + j];
        g_len[s][b] = (int)(acc + 0.5f);
    }
}

// ---------------- masked context + norms ----------------
__global__ __launch_bounds__(256) void k_prep(
    const float* __restrict__ ctx1, const float* __restrict__ m1,
    const float* __restrict__ ctx2, const float* __restrict__ m2,
    const float* __restrict__ w_mp)
{
    int i = blockIdx.x, b = blockIdx.y, s = blockIdx.z;
    const float* ctx = s ? ctx2 : ctx1;
    const float* mk  = s ? m2   : m1;
    __shared__ float cs[H_];
    float m = mk[b*L_ + i];
    int tid = threadIdx.x;
    float* cdst = g_c[s] + (size_t)(b*L_ + i) * H_;
    const float* csrc = ctx + (size_t)(b*L_ + i) * H_;
    for (int h = tid; h < H_; h += 256) {
        float v = csrc[h] * m;
        cs[h] = v;
        cdst[h] = v;
    }
    __syncthreads();
    int w = tid >> 5, lane = tid & 31;
    for (int t = w; t < NCH; t += 8) {
        float acc = 0.f;
        #pragma unroll
        for (int k = 0; k < H_/32; k++) {
            int h = lane + 32*k;
            float c = cs[h];
            float x = (t < P_) ? w_mp[t*H_ + h] * c : c;
            acc = fmaf(x, x, acc);
        }
        #pragma unroll
        for (int o = 16; o; o >>= 1) acc += __shfl_xor_sync(0xffffffffu, acc, o);
        if (lane == 0) {
            if (t == P_) g_n[s][b*L_ + i] = sqrtf(acc);
            else         g_nw[s][(b*L_ + i)*P_ + t] = sqrtf(acc);
        }
    }
}

// ---------------- 17-channel pairwise GEMM fused with masked reductions ----------------
__global__ __launch_bounds__(256) void k_gemm(
    const float* __restrict__ w_mp,
    const float* __restrict__ m1, const float* __restrict__ m2,
    float* __restrict__ out)
{
    int p = blockIdx.x, b = blockIdx.y;
    const float* A  = g_c[0] + (size_t)b * L_ * H_;
    const float* Bm = g_c[1] + (size_t)b * L_ * H_;
    __shared__ __align__(16) float As[16][128];
    __shared__ __align__(16) float Bs[16][128];
    __shared__ float mA[L_], mB[L_];
    __shared__ float red[16][132];
    int tid = threadIdx.x;
    if (tid < 128) mA[tid] = m1[b*L_ + tid];
    else           mB[tid-128] = m2[b*L_ + tid - 128];

    int lr = tid & 127, lk = (tid >> 7) << 3;
    int tr = tid >> 4,  tc = tid & 15;
    const bool wt = (p < P_);
    const float* wp = w_mp + p * H_;

    ull acc[8][4];
    #pragma unroll
    for (int r = 0; r < 8; r++)
        #pragma unroll
        for (int q = 0; q < 4; q++) acc[r][q] = 0ull;

    unsigned int bs_b = (unsigned int)__cvta_generic_to_shared(&Bs[0][0]);

    float4 pa0, pa1, pb0, pb1;
    {
        const float* Ap = A  + (size_t)lr * H_ + lk;
        const float* Bp = Bm + (size_t)lr * H_ + lk;
        pa0 = *(const float4*)(Ap);     pa1 = *(const float4*)(Ap + 4);
        pb0 = *(const float4*)(Bp);     pb1 = *(const float4*)(Bp + 4);
        if (wt) {
            float4 w0 = *(const float4*)(wp + lk);
            float4 w1 = *(const float4*)(wp + lk + 4);
            pa0.x*=w0.x; pa0.y*=w0.y; pa0.z*=w0.z; pa0.w*=w0.w;
            pa1.x*=w1.x; pa1.y*=w1.y; pa1.z*=w1.z; pa1.w*=w1.w;
            pb0.x*=w0.x; pb0.y*=w0.y; pb0.z*=w0.z; pb0.w*=w0.w;
            pb1.x*=w1.x; pb1.y*=w1.y; pb1.z*=w1.z; pb1.w*=w1.w;
        }
    }

    for (int c = 0; c < H_/16; c++) {
        As[lk+0][lr]=pa0.x; As[lk+1][lr]=pa0.y; As[lk+2][lr]=pa0.z; As[lk+3][lr]=pa0.w;
        As[lk+4][lr]=pa1.x; As[lk+5][lr]=pa1.y; As[lk+6][lr]=pa1.z; As[lk+7][lr]=pa1.w;
        Bs[lk+0][lr]=pb0.x; Bs[lk+1][lr]=pb0.y; Bs[lk+2][lr]=pb0.z; Bs[lk+3][lr]=pb0.w;
        Bs[lk+4][lr]=pb1.x; Bs[lk+5][lr]=pb1.y; Bs[lk+6][lr]=pb1.z; Bs[lk+7][lr]=pb1.w;
        __syncthreads();
        if (c + 1 < H_/16) {
            int k0 = (c + 1) * 16;
            const float* Ap = A  + (size_t)lr * H_ + k0 + lk;
            const float* Bp = Bm + (size_t)lr * H_ + k0 + lk;
            pa0 = *(const float4*)(Ap);     pa1 = *(const float4*)(Ap + 4);
            pb0 = *(const float4*)(Bp);     pb1 = *(const float4*)(Bp + 4);
            if (wt) {
                float4 w0 = *(const float4*)(wp + k0 + lk);
                float4 w1 = *(const float4*)(wp + k0 + lk + 4);
                pa0.x*=w0.x; pa0.y*=w0.y; pa0.z*=w0.z; pa0.w*=w0.w;
                pa1.x*=w1.x; pa1.y*=w1.y; pa1.z*=w1.z; pa1.w*=w1.w;
                pb0.x*=w0.x; pb0.y*=w0.y; pb0.z*=w0.z; pb0.w*=w0.w;
                pb1.x*=w1.x; pb1.y*=w1.y; pb1.z*=w1.z; pb1.w*=w1.w;
            }
        }
        #pragma unroll
        for (int k = 0; k < 16; k++) {
            float4 ra0 = *(const float4*)&As[k][tr << 3];
            float4 ra1 = *(const float4*)&As[k][(tr << 3) + 4];
            unsigned int bb = bs_b + (unsigned int)((((k << 7) + (tc << 1))) << 2);
            ull b0 = lds64(bb);
            ull b1 = lds64(bb + 32*4);
            ull b2 = lds64(bb + 64*4);
            ull b3 = lds64(bb + 96*4);
            float av[8] = {ra0.x, ra0.y, ra0.z, ra0.w, ra1.x, ra1.y, ra1.z, ra1.w};
            #pragma unroll
            for (int r = 0; r < 8; r++) {
                ull aa; PACK2(aa, av[r]);
                FMA2(acc[r][0], aa, b0);
                FMA2(acc[r][1], aa, b1);
                FMA2(acc[r][2], aa, b2);
                FMA2(acc[r][3], aa, b3);
            }
        }
        __syncthreads();
    }

    float val[8][8];
    #pragma unroll
    for (int r = 0; r < 8; r++)
        #pragma unroll
        for (int q = 0; q < 4; q++)
            UNPK2(val[r][2*q], val[r][2*q+1], acc[r][q]);

    if (wt) {
        float dl[8], dr[8];
        #pragma unroll
        for (int r = 0; r < 8; r++) dl[r] = g_nw[0][(b*L_ + (tr*8 + r))*P_ + p];
        #pragma unroll
        for (int q = 0; q < 4; q++) {
            dr[2*q]   = g_nw[1][(b*L_ + tc*2 + 32*q    )*P_ + p];
            dr[2*q+1] = g_nw[1][(b*L_ + tc*2 + 32*q + 1)*P_ + p];
        }
        #pragma unroll
        for (int r = 0; r < 8; r++)
            #pragma unroll
            for (int cc = 0; cc < 8; cc++)
                val[r][cc] /= fmaxf(dl[r] * dr[cc], EPSF);
    } else {
        float dl[8], dr[8];
        #pragma unroll
        for (int r = 0; r < 8; r++) dl[r] = fmaxf(g_n[0][b*L_ + tr*8 + r], EPSF);
        #pragma unroll
        for (int q = 0; q < 4; q++) {
            dr[2*q]   = fmaxf(g_n[1][b*L_ + tc*2 + 32*q    ], EPSF);
            dr[2*q+1] = fmaxf(g_n[1][b*L_ + tc*2 + 32*q + 1], EPSF);
        }
        #pragma unroll
        for (int r = 0; r < 8; r++)
            #pragma unroll
            for (int cc = 0; cc < 8; cc++)
                val[r][cc] /= (dl[r] * dr[cc]);
    }

    float rm[8], cmk[8];
    #pragma unroll
    for (int r = 0; r < 8; r++) rm[r] = mA[tr*8 + r];
    #pragma unroll
    for (int q = 0; q < 4; q++) {
        cmk[2*q]   = mB[tc*2 + 32*q];
        cmk[2*q+1] = mB[tc*2 + 32*q + 1];
    }
    float cnt2 = fmaxf((float)g_len[1][b], EPSF);
    float cnt1 = fmaxf((float)g_len[0][b], EPSF);

    if (!wt) {
        #pragma unroll
        for (int r = 0; r < 8; r++) {
            float* dst = g_Scos + ((size_t)(b*L_ + tr*8 + r)) * L_;
            #pragma unroll
            for (int q = 0; q < 4; q++)
                *(float2*)(dst + tc*2 + 32*q) = make_float2(val[r][2*q], val[r][2*q+1]);
        }
    }

    #pragma unroll
    for (int r = 0; r < 8; r++) {
        float mx = NEGINF, sm = 0.f;
        #pragma unroll
        for (int cc = 0; cc < 8; cc++)
            if (cmk[cc] != 0.f) { mx = fmaxf(mx, val[r][cc]); sm += val[r][cc]; }
        #pragma unroll
        for (int o = 8; o; o >>= 1) {
            mx = fmaxf(mx, __shfl_xor_sync(0xffffffffu, mx, o));
            sm += __shfl_xor_sync(0xffffffffu, sm, o);
        }
        if (tc == 0) {
            int i = tr*8 + r;
            float* o_ = out + ((size_t)(b*2 + 0)*L_ + i) * OUTD;
            float mean = sm / cnt2;
            if (!wt) { o_[0] = mx; o_[1] = mean; }
            else     { o_[36 + p] = mx; o_[52 + p] = mean; }
        }
    }

    float cmx[8], csm[8];
    #pragma unroll
    for (int cc = 0; cc < 8; cc++) { cmx[cc] = NEGINF; csm[cc] = 0.f; }
    #pragma unroll
    for (int r = 0; r < 8; r++)
        if (rm[r] != 0.f)
            #pragma unroll
            for (int cc = 0; cc < 8; cc++) {
                cmx[cc] = fmaxf(cmx[cc], val[r][cc]);
                csm[cc] += val[r][cc];
            }

    #pragma unroll
    for (int q = 0; q < 4; q++) {
        red[tr][tc*2 + 32*q]     = cmx[2*q];
        red[tr][tc*2 + 32*q + 1] = cmx[2*q+1];
    }
    __syncthreads();
    float fmx = NEGINF;
    if (tid < 128) {
        fmx = red[0][tid];
        #pragma unroll
        for (int t = 1; t < 16; t++) fmx = fmaxf(fmx, red[t][tid]);
    }
    __syncthreads();
    #pragma unroll
    for (int q = 0; q < 4; q++) {
        red[tr][tc*2 + 32*q]     = csm[2*q];
        red[tr][tc*2 + 32*q + 1] = csm[2*q+1];
    }
    __syncthreads();
    if (tid < 128) {
        float fsm = 0.f;
        #pragma unroll
        for (int t = 0; t < 16; t++) fsm += red[t][tid];
        float* o_ = out + ((size_t)(b*2 + 1)*L_ + tid) * OUTD;
        float mean = fsm / cnt1;
        if (!wt) { o_[0] = fmx; o_[1] = mean; }
        else     { o_[36 + p] = fmx; o_[52 + p] = mean; }
    }
}

// ---------------- attention sums/maxes + fused softmax (packed f32x2, 384 thr) ----------------
// grid (L/TT, B, 2); each thread owns 2 consecutive h, block spans full H.
__global__ __launch_bounds__(ATT_THR) void k_att(
    const float* __restrict__ m1, const float* __restrict__ m2)
{
    int tb = blockIdx.x, b = blockIdx.y, s = blockIdx.z;
    int other = 1 - s;
    int lenO = g_len[other][b];
    const float* C = g_c[other] + (size_t)b * L_ * H_;
    const float* Scos = g_Scos + (size_t)b * L_ * L_;
    const float* mkS = s ? m2 : m1;
    __shared__ __align__(16) ull cw2[TT][L_];       // {w,w} duplicated pairs
    __shared__ float rmx[TT][ATT_W], rsm[TT][ATT_W];
    int tid = threadIdx.x;
    for (int idx = tid; idx < TT*L_; idx += ATT_THR) {
        int tt = idx >> 7, u = idx & (L_-1);
        int t = tb*TT + tt;
        float w = (s == 0) ? Scos[(size_t)t * L_ + u] : Scos[(size_t)u * L_ + t];
        ull ww; PACK2(ww, w);
        cw2[tt][u] = ww;
    }
    __syncthreads();

    unsigned int cw_b = (unsigned int)__cvta_generic_to_shared(&cw2[0][0]);
    ull sm2[TT];
    float mxl[TT], mxh[TT];
    #pragma unroll
    for (int tt = 0; tt < TT; tt++) { sm2[tt] = 0ull; mxl[tt] = NEGINF; mxh[tt] = NEGINF; }

    const float* Cp = C + 2*tid;
    for (int u = 0; u < lenO; u++) {
        ull cc = ldg64(Cp + (size_t)u * H_);
        unsigned int ub = cw_b + (unsigned int)(u << 3);
        #pragma unroll
        for (int tt = 0; tt < TT; tt++) {
            ull ww = lds64(ub + (unsigned int)(tt * (L_*8)));
            ull pp; MUL2(pp, ww, cc);
            FMA2(sm2[tt], ww, cc);
            float pl, ph; UNPK2(pl, ph, pp);
            mxl[tt] = fmaxf(mxl[tt], pl);
            mxh[tt] = fmaxf(mxh[tt], ph);
        }
    }

    int w = tid >> 5, lane = tid & 31;
    // store maxes
    #pragma unroll
    for (int tt = 0; tt < TT; tt++) {
        int t = tb*TT + tt;
        size_t base = ((size_t)(b*L_ + t)) * H_;
        *(float2*)(&g_attM[s][base + 2*tid]) = make_float2(mxl[tt], mxh[tt]);
    }

    // fused softmax: stage per-warp partial maxes for all tokens, one sync
    float s0[TT], s1[TT];
    #pragma unroll
    for (int tt = 0; tt < TT; tt++) {
        UNPK2(s0[tt], s1[tt], sm2[tt]);
        float lm = fmaxf(s0[tt], s1[tt]);
        #pragma unroll
        for (int o = 16; o; o >>= 1) lm = fmaxf(lm, __shfl_xor_sync(0xffffffffu, lm, o));
        if (lane == 0) rmx[tt][w] = lm;
    }
    __syncthreads();
    float bm[TT];
    #pragma unroll
    for (int tt = 0; tt < TT; tt++) {
        float m = rmx[tt][0];
        #pragma unroll
        for (int i = 1; i < ATT_W; i++) m = fmaxf(m, rmx[tt][i]);
        bm[tt] = m;
    }
    float e0[TT], e1[TT];
    #pragma unroll
    for (int tt = 0; tt < TT; tt++) {
        e0[tt] = expf(s0[tt] - bm[tt]);
        e1[tt] = expf(s1[tt] - bm[tt]);
        float ls = e0[tt] + e1[tt];
        #pragma unroll
        for (int o = 16; o; o >>= 1) ls += __shfl_xor_sync(0xffffffffu, ls, o);
        if (lane == 0) rsm[tt][w] = ls;
    }
    __syncthreads();
    #pragma unroll
    for (int tt = 0; tt < TT; tt++) {
        int t = tb*TT + tt;
        size_t base = ((size_t)(b*L_ + t)) * H_;
        float m = mkS[b*L_ + t];
        if (m == 0.f) {
            *(float2*)(&g_attS[s][base + 2*tid]) = make_float2(1.f/(float)H_, 1.f/(float)H_);
            continue;
        }
        float bs = 0.f;
        #pragma unroll
        for (int i = 0; i < ATT_W; i++) bs += rsm[tt][i];
        float inv = 1.f / bs;
        *(float2*)(&g_attS[s][base + 2*tid]) = make_float2(e0[tt]*inv, e1[tt]*inv);
    }
}

// ---------------- per-token weighted cosines (packed f32x2) ----------------
__global__ __launch_bounds__(256) void k_final(
    const float* __restrict__ wff, const float* __restrict__ wfb,
    const float* __restrict__ watt, const float* __restrict__ wmatt,
    float* __restrict__ out)
{
    int t = blockIdx.x, b = blockIdx.y, s = blockIdx.z;
    int other = 1 - s;
    __shared__ __align__(16) float sa[H_];
    __shared__ __align__(16) float sv[4][H_];
    int tid = threadIdx.x;
    const float* a = g_c[s] + ((size_t)(b*L_ + t)) * H_;
    int lenO = g_len[other][b];
    int lp = lenO > 0 ? lenO - 1 : 0;
    const float* v_ff  = g_c[other] + ((size_t)(b*L_ + lp)) * H_;
    const float* v_bf  = g_c[other] + ((size_t)(b*L_)) * H_;
    const float* v_am  = g_attS[s] + ((size_t)(b*L_ + t)) * H_;
    const float* v_amx = g_attM[s] + ((size_t)(b*L_ + t)) * H_;
    for (int h = tid; h < H_; h += 256) {
        sa[h] = a[h];
        sv[0][h] = v_ff[h];
        sv[1][h] = v_bf[h];
        sv[2][h] = v_am[h];
        sv[3][h] = v_amx[h];
    }
    __syncthreads();

    unsigned int sa_b = (unsigned int)__cvta_generic_to_shared(sa);
    unsigned int sv_b = (unsigned int)__cvta_generic_to_shared(&sv[0][0]);
    int w = tid >> 5, lane = tid & 31;
    float* o_ = out + ((size_t)(b*2 + s)*L_ + t) * OUTD;
    for (int task = w; task < 68; task += 8) {
        int q = task / 17;
        int tt = task - q * 17;
        const float* W = (q == 0) ? wff : (q == 1) ? wfb : (q == 2) ? watt : wmatt;
        int base = (q == 0) ? 2 : (q == 1) ? 19 : (q == 2) ? 68 : 85;
        const float* Wr = W + tt * H_;
        unsigned int svq = sv_b + (unsigned int)(q * H_ * 4);
        ull sav = 0ull, saa = 0ull, svv = 0ull;
        if (tt < P_) {
            #pragma unroll
            for (int k = 0; k < 12; k++) {
                int h2 = (lane + (k << 5)) << 1;
                ull a2 = lds64(sa_b + (unsigned int)(h2 << 2));
                ull v2 = lds64(svq  + (unsigned int)(h2 << 2));
                ull w2 = ldg64(Wr + h2);
                MUL2(a2, a2, w2);
                MUL2(v2, v2, w2);
                FMA2(sav, a2, v2);
                FMA2(saa, a2, a2);
                FMA2(svv, v2, v2);
            }
        } else {
            #pragma unroll
            for (int k = 0; k < 12; k++) {
                int h2 = (lane + (k << 5)) << 1;
                ull a2 = lds64(sa_b + (unsigned int)(h2 << 2));
                ull v2 = lds64(svq  + (unsigned int)(h2 << 2));
                FMA2(sav, a2, v2);
                FMA2(saa, a2, a2);
                FMA2(svv, v2, v2);
            }
        }
        float lo, hi, fsav, fsaa, fsvv;
        UNPK2(lo, hi, sav); fsav = lo + hi;
        UNPK2(lo, hi, saa); fsaa = lo + hi;
        UNPK2(lo, hi, svv); fsvv = lo + hi;
        #pragma unroll
        for (int o = 16; o; o >>= 1) {
            fsav += __shfl_xor_sync(0xffffffffu, fsav, o);
            fsaa += __shfl_xor_sync(0xffffffffu, fsaa, o);
            fsvv += __shfl_xor_sync(0xffffffffu, fsvv, o);
        }
        if (lane == 0) {
            float na = fmaxf(sqrtf(fsaa), EPSF);
            float nv = fmaxf(sqrtf(fsvv), EPSF);
            int col = (tt == P_) ? base : (base + 1 + tt);
            o_[col] = fsav / (na * nv);
        }
    }
}

// ---------------- launch ----------------
extern "C" void kernel_launch(void* const* d_in, const int* in_sizes, int n_in,
                              void* d_out, int out_size) {
    const float* c1    = (const float*)d_in[0];
    const float* m1    = (const float*)d_in[1];
    const float* c2    = (const float*)d_in[2];
    const float* m2    = (const float*)d_in[3];
    const float* wff   = (const float*)d_in[4];
    const float* wfb   = (const float*)d_in[5];
    const float* wmp   = (const float*)d_in[6];
    const float* watt  = (const float*)d_in[7];
    const float* wmatt = (const float*)d_in[8];
    float* out = (float*)d_out;
    (void)in_sizes; (void)n_in; (void)out_size;

    k_len    <<<1, 64>>>(m1, m2);
    k_prep   <<<dim3(L_, B_, 2), 256>>>(c1, m1, c2, m2, wmp);
    k_gemm   <<<dim3(NCH, B_), 256>>>(wmp, m1, m2, out);
    k_att    <<<dim3(L_/TT, B_, 2), ATT_THR>>>(m1, m2);
    k_final  <<<dim3(L_, B_, 2), 256>>>(wff, wfb, watt, wmatt, out);
}

// round 10
// speedup vs baseline: 1.2132x; 1.0224x over previous
#include <cuda_runtime.h>
#include <math.h>

typedef unsigned long long ull;

// Problem constants (fixed by reference setup_inputs)
#define B_  8
#define L_  128
#define H_  768
#define P_  16
#define NCH 17          // 16 perspectives + plain cosine channel
#define OUTD 102
#define EPSF 1e-8f
#define NEGINF (-1e30f)
#define TT 8            // token tile for attention kernel (8 -> 256 blocks, 2/SM)
#define ATT_THR 384     // 384 threads = 768 h / 2 packed
#define ATT_W   12      // warps per att block

// ---------------- scratch (static device memory; no allocation) ----------------
__device__ float g_c[2][B_*L_*H_];      // masked contexts
__device__ float g_n[2][B_*L_];         // plain L2 norms
__device__ float g_nw[2][B_*L_*P_];     // w_mp-weighted norms
__device__ float g_Scos[B_*L_*L_];      // cosine channel only (for k_att)
__device__ float g_attS[2][B_*L_*H_];   // att softmax (att_mean)
__device__ float g_attM[2][B_*L_*H_];   // att maxes
__device__ int   g_len[2][B_];

// ---------------- packed fp32x2 helpers ----------------
#define FMA2(d,a,b)    asm("fma.rn.f32x2 %0, %1, %2, %0;" : "+l"(d) : "l"(a), "l"(b))
#define MUL2(d,a,b)    asm("mul.rn.f32x2 %0, %1, %2;" : "=l"(d) : "l"(a), "l"(b))
#define PACK2(d,x)     asm("mov.b64 %0, {%1, %2};" : "=l"(d) : "f"(x), "f"(x))
#define UNPK2(lo,hi,v) asm("mov.b64 {%0, %1}, %2;" : "=f"(lo), "=f"(hi) : "l"(v))

__device__ __forceinline__ ull lds64(unsigned int addr) {
    ull v; asm volatile("ld.shared.b64 %0, [%1];" : "=l"(v) : "r"(addr)); return v;
}
__device__ __forceinline__ ull ldg64(const float* p) {
    ull v; asm volatile("ld.global.nc.b64 %0, [%1];" : "=l"(v) : "l"(p)); return v;
}

// ---------------- lengths ----------------
__global__ void k_len(const float* __restrict__ m1, const float* __restrict__ m2) {
    int t = threadIdx.x;
    if (t < 16) {
        int s = t >> 3, b = t & 7;
        const float* mk = s ? m2 : m1;
        float acc = 0.f;
        for (int j = 0; j < L_; j++) acc += mk[b*L_ + j];
        g_len[s][b] = (int)(acc + 0.5f);
    }
}

// ---------------- masked context + norms ----------------
__global__ __launch_bounds__(256) void k_prep(
    const float* __restrict__ ctx1, const float* __restrict__ m1,
    const float* __restrict__ ctx2, const float* __restrict__ m2,
    const float* __restrict__ w_mp)
{
    int i = blockIdx.x, b = blockIdx.y, s = blockIdx.z;
    const float* ctx = s ? ctx2 : ctx1;
    const float* mk  = s ? m2   : m1;
    __shared__ float cs[H_];
    float m = mk[b*L_ + i];
    int tid = threadIdx.x;
    float* cdst = g_c[s] + (size_t)(b*L_ + i) * H_;
    const float* csrc = ctx + (size_t)(b*L_ + i) * H_;
    for (int h = tid; h < H_; h += 256) {
        float v = csrc[h] * m;
        cs[h] = v;
        cdst[h] = v;
    }
    __syncthreads();
    int w = tid >> 5, lane = tid & 31;
    for (int t = w; t < NCH; t += 8) {
        float acc = 0.f;
        #pragma unroll
        for (int k = 0; k < H_/32; k++) {
            int h = lane + 32*k;
            float c = cs[h];
            float x = (t < P_) ? w_mp[t*H_ + h] * c : c;
            acc = fmaf(x, x, acc);
        }
        #pragma unroll
        for (int o = 16; o; o >>= 1) acc += __shfl_xor_sync(0xffffffffu, acc, o);
        if (lane == 0) {
            if (t == P_) g_n[s][b*L_ + i] = sqrtf(acc);
            else         g_nw[s][(b*L_ + i)*P_ + t] = sqrtf(acc);
        }
    }
}

// ---------------- 17-channel pairwise GEMM fused with masked reductions ----------------
__global__ __launch_bounds__(256) void k_gemm(
    const float* __restrict__ w_mp,
    const float* __restrict__ m1, const float* __restrict__ m2,
    float* __restrict__ out)
{
    int p = blockIdx.x, b = blockIdx.y;
    const float* A  = g_c[0] + (size_t)b * L_ * H_;
    const float* Bm = g_c[1] + (size_t)b * L_ * H_;
    __shared__ __align__(16) float As[16][128];
    __shared__ __align__(16) float Bs[16][128];
    __shared__ float mA[L_], mB[L_];
    __shared__ float red[16][132];
    int tid = threadIdx.x;
    if (tid < 128) mA[tid] = m1[b*L_ + tid];
    else           mB[tid-128] = m2[b*L_ + tid - 128];

    int lr = tid & 127, lk = (tid >> 7) << 3;
    int tr = tid >> 4,  tc = tid & 15;
    const bool wt = (p < P_);
    const float* wp = w_mp + p * H_;

    ull acc[8][4];
    #pragma unroll
    for (int r = 0; r < 8; r++)
        #pragma unroll
        for (int q = 0; q < 4; q++) acc[r][q] = 0ull;

    unsigned int bs_b = (unsigned int)__cvta_generic_to_shared(&Bs[0][0]);

    float4 pa0, pa1, pb0, pb1;
    {
        const float* Ap = A  + (size_t)lr * H_ + lk;
        const float* Bp = Bm + (size_t)lr * H_ + lk;
        pa0 = *(const float4*)(Ap);     pa1 = *(const float4*)(Ap + 4);
        pb0 = *(const float4*)(Bp);     pb1 = *(const float4*)(Bp + 4);
        if (wt) {
            float4 w0 = *(const float4*)(wp + lk);
            float4 w1 = *(const float4*)(wp + lk + 4);
            pa0.x*=w0.x; pa0.y*=w0.y; pa0.z*=w0.z; pa0.w*=w0.w;
            pa1.x*=w1.x; pa1.y*=w1.y; pa1.z*=w1.z; pa1.w*=w1.w;
            pb0.x*=w0.x; pb0.y*=w0.y; pb0.z*=w0.z; pb0.w*=w0.w;
            pb1.x*=w1.x; pb1.y*=w1.y; pb1.z*=w1.z; pb1.w*=w1.w;
        }
    }

    for (int c = 0; c < H_/16; c++) {
        As[lk+0][lr]=pa0.x; As[lk+1][lr]=pa0.y; As[lk+2][lr]=pa0.z; As[lk+3][lr]=pa0.w;
        As[lk+4][lr]=pa1.x; As[lk+5][lr]=pa1.y; As[lk+6][lr]=pa1.z; As[lk+7][lr]=pa1.w;
        Bs[lk+0][lr]=pb0.x; Bs[lk+1][lr]=pb0.y; Bs[lk+2][lr]=pb0.z; Bs[lk+3][lr]=pb0.w;
        Bs[lk+4][lr]=pb1.x; Bs[lk+5][lr]=pb1.y; Bs[lk+6][lr]=pb1.z; Bs[lk+7][lr]=pb1.w;
        __syncthreads();
        if (c + 1 < H_/16) {
            int k0 = (c + 1) * 16;
            const float* Ap = A  + (size_t)lr * H_ + k0 + lk;
            const float* Bp = Bm + (size_t)lr * H_ + k0 + lk;
            pa0 = *(const float4*)(Ap);     pa1 = *(const float4*)(Ap + 4);
            pb0 = *(const float4*)(Bp);     pb1 = *(const float4*)(Bp + 4);
            if (wt) {
                float4 w0 = *(const float4*)(wp + k0 + lk);
                float4 w1 = *(const float4*)(wp + k0 + lk + 4);
                pa0.x*=w0.x; pa0.y*=w0.y; pa0.z*=w0.z; pa0.w*=w0.w;
                pa1.x*=w1.x; pa1.y*=w1.y; pa1.z*=w1.z; pa1.w*=w1.w;
                pb0.x*=w0.x; pb0.y*=w0.y; pb0.z*=w0.z; pb0.w*=w0.w;
                pb1.x*=w1.x; pb1.y*=w1.y; pb1.z*=w1.z; pb1.w*=w1.w;
            }
        }
        #pragma unroll
        for (int k = 0; k < 16; k++) {
            float4 ra0 = *(const float4*)&As[k][tr << 3];
            float4 ra1 = *(const float4*)&As[k][(tr << 3) + 4];
            unsigned int bb = bs_b + (unsigned int)((((k << 7) + (tc << 1))) << 2);
            ull b0 = lds64(bb);
            ull b1 = lds64(bb + 32*4);
            ull b2 = lds64(bb + 64*4);
            ull b3 = lds64(bb + 96*4);
            float av[8] = {ra0.x, ra0.y, ra0.z, ra0.w, ra1.x, ra1.y, ra1.z, ra1.w};
            #pragma unroll
            for (int r = 0; r < 8; r++) {
                ull aa; PACK2(aa, av[r]);
                FMA2(acc[r][0], aa, b0);
                FMA2(acc[r][1], aa, b1);
                FMA2(acc[r][2], aa, b2);
                FMA2(acc[r][3], aa, b3);
            }
        }
        __syncthreads();
    }

    float val[8][8];
    #pragma unroll
    for (int r = 0; r < 8; r++)
        #pragma unroll
        for (int q = 0; q < 4; q++)
            UNPK2(val[r][2*q], val[r][2*q+1], acc[r][q]);

    if (wt) {
        float dl[8], dr[8];
        #pragma unroll
        for (int r = 0; r < 8; r++) dl[r] = g_nw[0][(b*L_ + (tr*8 + r))*P_ + p];
        #pragma unroll
        for (int q = 0; q < 4; q++) {
            dr[2*q]   = g_nw[1][(b*L_ + tc*2 + 32*q    )*P_ + p];
            dr[2*q+1] = g_nw[1][(b*L_ + tc*2 + 32*q + 1)*P_ + p];
        }
        #pragma unroll
        for (int r = 0; r < 8; r++)
            #pragma unroll
            for (int cc = 0; cc < 8; cc++)
                val[r][cc] /= fmaxf(dl[r] * dr[cc], EPSF);
    } else {
        float dl[8], dr[8];
        #pragma unroll
        for (int r = 0; r < 8; r++) dl[r] = fmaxf(g_n[0][b*L_ + tr*8 + r], EPSF);
        #pragma unroll
        for (int q = 0; q < 4; q++) {
            dr[2*q]   = fmaxf(g_n[1][b*L_ + tc*2 + 32*q    ], EPSF);
            dr[2*q+1] = fmaxf(g_n[1][b*L_ + tc*2 + 32*q + 1], EPSF);
        }
        #pragma unroll
        for (int r = 0; r < 8; r++)
            #pragma unroll
            for (int cc = 0; cc < 8; cc++)
                val[r][cc] /= (dl[r] * dr[cc]);
    }

    float rm[8], cmk[8];
    #pragma unroll
    for (int r = 0; r < 8; r++) rm[r] = mA[tr*8 + r];
    #pragma unroll
    for (int q = 0; q < 4; q++) {
        cmk[2*q]   = mB[tc*2 + 32*q];
        cmk[2*q+1] = mB[tc*2 + 32*q + 1];
    }
    float cnt2 = fmaxf((float)g_len[1][b], EPSF);
    float cnt1 = fmaxf((float)g_len[0][b], EPSF);

    if (!wt) {
        #pragma unroll
        for (int r = 0; r < 8; r++) {
            float* dst = g_Scos + ((size_t)(b*L_ + tr*8 + r)) * L_;
            #pragma unroll
            for (int q = 0; q < 4; q++)
                *(float2*)(dst + tc*2 + 32*q) = make_float2(val[r][2*q], val[r][2*q+1]);
        }
    }

    #pragma unroll
    for (int r = 0; r < 8; r++) {
        float mx = NEGINF, sm = 0.f;
        #pragma unroll
        for (int cc = 0; cc < 8; cc++)
            if (cmk[cc] != 0.f) { mx = fmaxf(mx, val[r][cc]); sm += val[r][cc]; }
        #pragma unroll
        for (int o = 8; o; o >>= 1) {
            mx = fmaxf(mx, __shfl_xor_sync(0xffffffffu, mx, o));
            sm += __shfl_xor_sync(0xffffffffu, sm, o);
        }
        if (tc == 0) {
            int i = tr*8 + r;
            float* o_ = out + ((size_t)(b*2 + 0)*L_ + i) * OUTD;
            float mean = sm / cnt2;
            if (!wt) { o_[0] = mx; o_[1] = mean; }
            else     { o_[36 + p] = mx; o_[52 + p] = mean; }
        }
    }

    float cmx[8], csm[8];
    #pragma unroll
    for (int cc = 0; cc < 8; cc++) { cmx[cc] = NEGINF; csm[cc] = 0.f; }
    #pragma unroll
    for (int r = 0; r < 8; r++)
        if (rm[r] != 0.f)
            #pragma unroll
            for (int cc = 0; cc < 8; cc++) {
                cmx[cc] = fmaxf(cmx[cc], val[r][cc]);
                csm[cc] += val[r][cc];
            }

    #pragma unroll
    for (int q = 0; q < 4; q++) {
        red[tr][tc*2 + 32*q]     = cmx[2*q];
        red[tr][tc*2 + 32*q + 1] = cmx[2*q+1];
    }
    __syncthreads();
    float fmx = NEGINF;
    if (tid < 128) {
        fmx = red[0][tid];
        #pragma unroll
        for (int t = 1; t < 16; t++) fmx = fmaxf(fmx, red[t][tid]);
    }
    __syncthreads();
    #pragma unroll
    for (int q = 0; q < 4; q++) {
        red[tr][tc*2 + 32*q]     = csm[2*q];
        red[tr][tc*2 + 32*q + 1] = csm[2*q+1];
    }
    __syncthreads();
    if (tid < 128) {
        float fsm = 0.f;
        #pragma unroll
        for (int t = 0; t < 16; t++) fsm += red[t][tid];
        float* o_ = out + ((size_t)(b*2 + 1)*L_ + tid) * OUTD;
        float mean = fsm / cnt1;
        if (!wt) { o_[0] = fmx; o_[1] = mean; }
        else     { o_[36 + p] = fmx; o_[52 + p] = mean; }
    }
}

// ---------------- attention sums/maxes + fused softmax (packed f32x2) ----------------
// grid (L/TT=16, B, 2) = 256 blocks; 2 blocks/SM; prefetched C stream.
__global__ __launch_bounds__(ATT_THR, 2) void k_att(
    const float* __restrict__ m1, const float* __restrict__ m2)
{
    int tb = blockIdx.x, b = blockIdx.y, s = blockIdx.z;
    int other = 1 - s;
    int lenO = g_len[other][b];           // always >= 64
    const float* C = g_c[other] + (size_t)b * L_ * H_;
    const float* Scos = g_Scos + (size_t)b * L_ * L_;
    const float* mkS = s ? m2 : m1;
    __shared__ __align__(16) ull cw2[TT][L_];       // {w,w} duplicated pairs
    __shared__ float rmx[TT][ATT_W], rsm[TT][ATT_W];
    int tid = threadIdx.x;
    for (int idx = tid; idx < TT*L_; idx += ATT_THR) {
        int tt = idx >> 7, u = idx & (L_-1);
        int t = tb*TT + tt;
        float w = (s == 0) ? Scos[(size_t)t * L_ + u] : Scos[(size_t)u * L_ + t];
        ull ww; PACK2(ww, w);
        cw2[tt][u] = ww;
    }
    __syncthreads();

    unsigned int cw_b = (unsigned int)__cvta_generic_to_shared(&cw2[0][0]);
    ull sm2[TT];
    float mxl[TT], mxh[TT];
    #pragma unroll
    for (int tt = 0; tt < TT; tt++) { sm2[tt] = 0ull; mxl[tt] = NEGINF; mxh[tt] = NEGINF; }

    const float* Cp = C + 2*tid;
    ull cc = ldg64(Cp);                   // prefetch u=0
    for (int u = 0; u < lenO; u++) {
        ull cur = cc;
        if (u + 1 < lenO) cc = ldg64(Cp + (size_t)(u+1) * H_);
        unsigned int ub = cw_b + (unsigned int)(u << 3);
        #pragma unroll
        for (int tt = 0; tt < TT; tt++) {
            ull ww = lds64(ub + (unsigned int)(tt * (L_*8)));
            ull pp; MUL2(pp, ww, cur);
            FMA2(sm2[tt], ww, cur);
            float pl, ph; UNPK2(pl, ph, pp);
            mxl[tt] = fmaxf(mxl[tt], pl);
            mxh[tt] = fmaxf(mxh[tt], ph);
        }
    }

    int w = tid >> 5, lane = tid & 31;
    // store maxes
    #pragma unroll
    for (int tt = 0; tt < TT; tt++) {
        int t = tb*TT + tt;
        size_t base = ((size_t)(b*L_ + t)) * H_;
        *(float2*)(&g_attM[s][base + 2*tid]) = make_float2(mxl[tt], mxh[tt]);
    }

    // fused softmax: stage per-warp partial maxes for all tokens, one sync
    float s0[TT], s1[TT];
    #pragma unroll
    for (int tt = 0; tt < TT; tt++) {
        UNPK2(s0[tt], s1[tt], sm2[tt]);
        float lm = fmaxf(s0[tt], s1[tt]);
        #pragma unroll
        for (int o = 16; o; o >>= 1) lm = fmaxf(lm, __shfl_xor_sync(0xffffffffu, lm, o));
        if (lane == 0) rmx[tt][w] = lm;
    }
    __syncthreads();
    float bm[TT];
    #pragma unroll
    for (int tt = 0; tt < TT; tt++) {
        float m = rmx[tt][0];
        #pragma unroll
        for (int i = 1; i < ATT_W; i++) m = fmaxf(m, rmx[tt][i]);
        bm[tt] = m;
    }
    float e0[TT], e1[TT];
    #pragma unroll
    for (int tt = 0; tt < TT; tt++) {
        e0[tt] = expf(s0[tt] - bm[tt]);
        e1[tt] = expf(s1[tt] - bm[tt]);
        float ls = e0[tt] + e1[tt];
        #pragma unroll
        for (int o = 16; o; o >>= 1) ls += __shfl_xor_sync(0xffffffffu, ls, o);
        if (lane == 0) rsm[tt][w] = ls;
    }
    __syncthreads();
    #pragma unroll
    for (int tt = 0; tt < TT; tt++) {
        int t = tb*TT + tt;
        size_t base = ((size_t)(b*L_ + t)) * H_;
        float m = mkS[b*L_ + t];
        if (m == 0.f) {
            *(float2*)(&g_attS[s][base + 2*tid]) = make_float2(1.f/(float)H_, 1.f/(float)H_);
            continue;
        }
        float bs = 0.f;
        #pragma unroll
        for (int i = 0; i < ATT_W; i++) bs += rsm[tt][i];
        float inv = 1.f / bs;
        *(float2*)(&g_attS[s][base + 2*tid]) = make_float2(e0[tt]*inv, e1[tt]*inv);
    }
}

// ---------------- per-token weighted cosines (packed f32x2) ----------------
__global__ __launch_bounds__(256) void k_final(
    const float* __restrict__ wff, const float* __restrict__ wfb,
    const float* __restrict__ watt, const float* __restrict__ wmatt,
    float* __restrict__ out)
{
    int t = blockIdx.x, b = blockIdx.y, s = blockIdx.z;
    int other = 1 - s;
    __shared__ __align__(16) float sa[H_];
    __shared__ __align__(16) float sv[4][H_];
    int tid = threadIdx.x;
    const float* a = g_c[s] + ((size_t)(b*L_ + t)) * H_;
    int lenO = g_len[other][b];
    int lp = lenO > 0 ? lenO - 1 : 0;
    const float* v_ff  = g_c[other] + ((size_t)(b*L_ + lp)) * H_;
    const float* v_bf  = g_c[other] + ((size_t)(b*L_)) * H_;
    const float* v_am  = g_attS[s] + ((size_t)(b*L_ + t)) * H_;
    const float* v_amx = g_attM[s] + ((size_t)(b*L_ + t)) * H_;
    for (int h = tid; h < H_; h += 256) {
        sa[h] = a[h];
        sv[0][h] = v_ff[h];
        sv[1][h] = v_bf[h];
        sv[2][h] = v_am[h];
        sv[3][h] = v_amx[h];
    }
    __syncthreads();

    unsigned int sa_b = (unsigned int)__cvta_generic_to_shared(sa);
    unsigned int sv_b = (unsigned int)__cvta_generic_to_shared(&sv[0][0]);
    int w = tid >> 5, lane = tid & 31;
    float* o_ = out + ((size_t)(b*2 + s)*L_ + t) * OUTD;
    for (int task = w; task < 68; task += 8) {
        int q = task / 17;
        int tt = task - q * 17;
        const float* W = (q == 0) ? wff : (q == 1) ? wfb : (q == 2) ? watt : wmatt;
        int base = (q == 0) ? 2 : (q == 1) ? 19 : (q == 2) ? 68 : 85;
        const float* Wr = W + tt * H_;
        unsigned int svq = sv_b + (unsigned int)(q * H_ * 4);
        ull sav = 0ull, saa = 0ull, svv = 0ull;
        if (tt < P_) {
            #pragma unroll
            for (int k = 0; k < 12; k++) {
                int h2 = (lane + (k << 5)) << 1;
                ull a2 = lds64(sa_b + (unsigned int)(h2 << 2));
                ull v2 = lds64(svq  + (unsigned int)(h2 << 2));
                ull w2 = ldg64(Wr + h2);
                MUL2(a2, a2, w2);
                MUL2(v2, v2, w2);
                FMA2(sav, a2, v2);
                FMA2(saa, a2, a2);
                FMA2(svv, v2, v2);
            }
        } else {
            #pragma unroll
            for (int k = 0; k < 12; k++) {
                int h2 = (lane + (k << 5)) << 1;
                ull a2 = lds64(sa_b + (unsigned int)(h2 << 2));
                ull v2 = lds64(svq  + (unsigned int)(h2 << 2));
                FMA2(sav, a2, v2);
                FMA2(saa, a2, a2);
                FMA2(svv, v2, v2);
            }
        }
        float lo, hi, fsav, fsaa, fsvv;
        UNPK2(lo, hi, sav); fsav = lo + hi;
        UNPK2(lo, hi, saa); fsaa = lo + hi;
        UNPK2(lo, hi, svv); fsvv = lo + hi;
        #pragma unroll
        for (int o = 16; o; o >>= 1) {
            fsav += __shfl_xor_sync(0xffffffffu, fsav, o);
            fsaa += __shfl_xor_sync(0xffffffffu, fsaa, o);
            fsvv += __shfl_xor_sync(0xffffffffu, fsvv, o);
        }
        if (lane == 0) {
            float na = fmaxf(sqrtf(fsaa), EPSF);
            float nv = fmaxf(sqrtf(fsvv), EPSF);
            int col = (tt == P_) ? base : (base + 1 + tt);
            o_[col] = fsav / (na * nv);
        }
    }
}

// ---------------- launch ----------------
extern "C" void kernel_launch(void* const* d_in, const int* in_sizes, int n_in,
                              void* d_out, int out_size) {
    const float* c1    = (const float*)d_in[0];
    const float* m1    = (const float*)d_in[1];
    const float* c2    = (const float*)d_in[2];
    const float* m2    = (const float*)d_in[3];
    const float* wff   = (const float*)d_in[4];
    const float* wfb   = (const float*)d_in[5];
    const float* wmp   = (const float*)d_in[6];
    const float* watt  = (const float*)d_in[7];
    const float* wmatt = (const float*)d_in[8];
    float* out = (float*)d_out;
    (void)in_sizes; (void)n_in; (void)out_size;

    k_len    <<<1, 64>>>(m1, m2);
    k_prep   <<<dim3(L_, B_, 2), 256>>>(c1, m1, c2, m2, wmp);
    k_gemm   <<<dim3(NCH, B_), 256>>>(wmp, m1, m2, out);
    k_att    <<<dim3(L_/TT, B_, 2), ATT_THR>>>(m1, m2);
    k_final  <<<dim3(L_, B_, 2), 256>>>(wff, wfb, watt, wmatt, out);
}

// round 11
// speedup vs baseline: 1.2228x; 1.0079x over previous
#include <cuda_runtime.h>
#include <math.h>

typedef unsigned long long ull;

// Problem constants (fixed by reference setup_inputs)
#define B_  8
#define L_  128
#define H_  768
#define P_  16
#define NCH 17          // 16 perspectives + plain cosine channel
#define OUTD 102
#define EPSF 1e-8f
#define NEGINF (-1e30f)
#define TT 16           // token tile for attention kernel (16 -> 128 blocks, balanced 1/SM)
#define ATT_THR 384     // 384 threads = 768 h / 2 packed
#define ATT_W   12      // warps per att block

// ---------------- scratch (static device memory; no allocation) ----------------
__device__ float g_c[2][B_*L_*H_];      // masked contexts
__device__ float g_n[2][B_*L_];         // plain L2 norms
__device__ float g_nw[2][B_*L_*P_];     // w_mp-weighted norms
__device__ float g_Scos[B_*L_*L_];      // cosine channel only (for k_att)
__device__ float g_attS[2][B_*L_*H_];   // att softmax (att_mean)
__device__ float g_attM[2][B_*L_*H_];   // att maxes
__device__ int   g_len[2][B_];

// ---------------- packed fp32x2 helpers ----------------
#define FMA2(d,a,b)    asm("fma.rn.f32x2 %0, %1, %2, %0;" : "+l"(d) : "l"(a), "l"(b))
#define MUL2(d,a,b)    asm("mul.rn.f32x2 %0, %1, %2;" : "=l"(d) : "l"(a), "l"(b))
#define PACK2(d,x)     asm("mov.b64 %0, {%1, %2};" : "=l"(d) : "f"(x), "f"(x))
#define UNPK2(lo,hi,v) asm("mov.b64 {%0, %1}, %2;" : "=f"(lo), "=f"(hi) : "l"(v))

__device__ __forceinline__ ull lds64(unsigned int addr) {
    ull v; asm volatile("ld.shared.b64 %0, [%1];" : "=l"(v) : "r"(addr)); return v;
}
__device__ __forceinline__ ull ldg64(const float* p) {
    ull v; asm volatile("ld.global.nc.b64 %0, [%1];" : "=l"(v) : "l"(p)); return v;
}

// ---------------- lengths ----------------
__global__ void k_len(const float* __restrict__ m1, const float* __restrict__ m2) {
    int t = threadIdx.x;
    if (t < 16) {
        int s = t >> 3, b = t & 7;
        const float* mk = s ? m2 : m1;
        float acc = 0.f;
        for (int j = 0; j < L_; j++) acc += mk[b*L_ + j];
        g_len[s][b] = (int)(acc + 0.5f);
    }
}

// ---------------- masked context + norms ----------------
__global__ __launch_bounds__(256) void k_prep(
    const float* __restrict__ ctx1, const float* __restrict__ m1,
    const float* __restrict__ ctx2, const float* __restrict__ m2,
    const float* __restrict__ w_mp)
{
    int i = blockIdx.x, b = blockIdx.y, s = blockIdx.z;
    const float* ctx = s ? ctx2 : ctx1;
    const float* mk  = s ? m2   : m1;
    __shared__ float cs[H_];
    float m = mk[b*L_ + i];
    int tid = threadIdx.x;
    float* cdst = g_c[s] + (size_t)(b*L_ + i) * H_;
    const float* csrc = ctx + (size_t)(b*L_ + i) * H_;
    for (int h = tid; h < H_; h += 256) {
        float v = csrc[h] * m;
        cs[h] = v;
        cdst[h] = v;
    }
    __syncthreads();
    int w = tid >> 5, lane = tid & 31;
    for (int t = w; t < NCH; t += 8) {
        float acc = 0.f;
        #pragma unroll
        for (int k = 0; k < H_/32; k++) {
            int h = lane + 32*k;
            float c = cs[h];
            float x = (t < P_) ? w_mp[t*H_ + h] * c : c;
            acc = fmaf(x, x, acc);
        }
        #pragma unroll
        for (int o = 16; o; o >>= 1) acc += __shfl_xor_sync(0xffffffffu, acc, o);
        if (lane == 0) {
            if (t == P_) g_n[s][b*L_ + i] = sqrtf(acc);
            else         g_nw[s][(b*L_ + i)*P_ + t] = sqrtf(acc);
        }
    }
}

// ---------------- 17-channel pairwise GEMM fused with masked reductions ----------------
__global__ __launch_bounds__(256) void k_gemm(
    const float* __restrict__ w_mp,
    const float* __restrict__ m1, const float* __restrict__ m2,
    float* __restrict__ out)
{
    int p = blockIdx.x, b = blockIdx.y;
    const float* A  = g_c[0] + (size_t)b * L_ * H_;
    const float* Bm = g_c[1] + (size_t)b * L_ * H_;
    __shared__ __align__(16) float As[16][128];
    __shared__ __align__(16) float Bs[16][128];
    __shared__ float mA[L_], mB[L_];
    __shared__ float red[16][132];
    int tid = threadIdx.x;
    if (tid < 128) mA[tid] = m1[b*L_ + tid];
    else           mB[tid-128] = m2[b*L_ + tid - 128];

    int lr = tid & 127, lk = (tid >> 7) << 3;
    int tr = tid >> 4,  tc = tid & 15;
    const bool wt = (p < P_);
    const float* wp = w_mp + p * H_;

    ull acc[8][4];
    #pragma unroll
    for (int r = 0; r < 8; r++)
        #pragma unroll
        for (int q = 0; q < 4; q++) acc[r][q] = 0ull;

    unsigned int bs_b = (unsigned int)__cvta_generic_to_shared(&Bs[0][0]);

    float4 pa0, pa1, pb0, pb1;
    {
        const float* Ap = A  + (size_t)lr * H_ + lk;
        const float* Bp = Bm + (size_t)lr * H_ + lk;
        pa0 = *(const float4*)(Ap);     pa1 = *(const float4*)(Ap + 4);
        pb0 = *(const float4*)(Bp);     pb1 = *(const float4*)(Bp + 4);
        if (wt) {
            float4 w0 = *(const float4*)(wp + lk);
            float4 w1 = *(const float4*)(wp + lk + 4);
            pa0.x*=w0.x; pa0.y*=w0.y; pa0.z*=w0.z; pa0.w*=w0.w;
            pa1.x*=w1.x; pa1.y*=w1.y; pa1.z*=w1.z; pa1.w*=w1.w;
            pb0.x*=w0.x; pb0.y*=w0.y; pb0.z*=w0.z; pb0.w*=w0.w;
            pb1.x*=w1.x; pb1.y*=w1.y; pb1.z*=w1.z; pb1.w*=w1.w;
        }
    }

    for (int c = 0; c < H_/16; c++) {
        As[lk+0][lr]=pa0.x; As[lk+1][lr]=pa0.y; As[lk+2][lr]=pa0.z; As[lk+3][lr]=pa0.w;
        As[lk+4][lr]=pa1.x; As[lk+5][lr]=pa1.y; As[lk+6][lr]=pa1.z; As[lk+7][lr]=pa1.w;
        Bs[lk+0][lr]=pb0.x; Bs[lk+1][lr]=pb0.y; Bs[lk+2][lr]=pb0.z; Bs[lk+3][lr]=pb0.w;
        Bs[lk+4][lr]=pb1.x; Bs[lk+5][lr]=pb1.y; Bs[lk+6][lr]=pb1.z; Bs[lk+7][lr]=pb1.w;
        __syncthreads();
        if (c + 1 < H_/16) {
            int k0 = (c + 1) * 16;
            const float* Ap = A  + (size_t)lr * H_ + k0 + lk;
            const float* Bp = Bm + (size_t)lr * H_ + k0 + lk;
            pa0 = *(const float4*)(Ap);     pa1 = *(const float4*)(Ap + 4);
            pb0 = *(const float4*)(Bp);     pb1 = *(const float4*)(Bp + 4);
            if (wt) {
                float4 w0 = *(const float4*)(wp + k0 + lk);
                float4 w1 = *(const float4*)(wp + k0 + lk + 4);
                pa0.x*=w0.x; pa0.y*=w0.y; pa0.z*=w0.z; pa0.w*=w0.w;
                pa1.x*=w1.x; pa1.y*=w1.y; pa1.z*=w1.z; pa1.w*=w1.w;
                pb0.x*=w0.x; pb0.y*=w0.y; pb0.z*=w0.z; pb0.w*=w0.w;
                pb1.x*=w1.x; pb1.y*=w1.y; pb1.z*=w1.z; pb1.w*=w1.w;
            }
        }
        #pragma unroll
        for (int k = 0; k < 16; k++) {
            float4 ra0 = *(const float4*)&As[k][tr << 3];
            float4 ra1 = *(const float4*)&As[k][(tr << 3) + 4];
            unsigned int bb = bs_b + (unsigned int)((((k << 7) + (tc << 1))) << 2);
            ull b0 = lds64(bb);
            ull b1 = lds64(bb + 32*4);
            ull b2 = lds64(bb + 64*4);
            ull b3 = lds64(bb + 96*4);
            float av[8] = {ra0.x, ra0.y, ra0.z, ra0.w, ra1.x, ra1.y, ra1.z, ra1.w};
            #pragma unroll
            for (int r = 0; r < 8; r++) {
                ull aa; PACK2(aa, av[r]);
                FMA2(acc[r][0], aa, b0);
                FMA2(acc[r][1], aa, b1);
                FMA2(acc[r][2], aa, b2);
                FMA2(acc[r][3], aa, b3);
            }
        }
        __syncthreads();
    }

    float val[8][8];
    #pragma unroll
    for (int r = 0; r < 8; r++)
        #pragma unroll
        for (int q = 0; q < 4; q++)
            UNPK2(val[r][2*q], val[r][2*q+1], acc[r][q]);

    if (wt) {
        float dl[8], dr[8];
        #pragma unroll
        for (int r = 0; r < 8; r++) dl[r] = g_nw[0][(b*L_ + (tr*8 + r))*P_ + p];
        #pragma unroll
        for (int q = 0; q < 4; q++) {
            dr[2*q]   = g_nw[1][(b*L_ + tc*2 + 32*q    )*P_ + p];
            dr[2*q+1] = g_nw[1][(b*L_ + tc*2 + 32*q + 1)*P_ + p];
        }
        #pragma unroll
        for (int r = 0; r < 8; r++)
            #pragma unroll
            for (int cc = 0; cc < 8; cc++)
                val[r][cc] /= fmaxf(dl[r] * dr[cc], EPSF);
    } else {
        float dl[8], dr[8];
        #pragma unroll
        for (int r = 0; r < 8; r++) dl[r] = fmaxf(g_n[0][b*L_ + tr*8 + r], EPSF);
        #pragma unroll
        for (int q = 0; q < 4; q++) {
            dr[2*q]   = fmaxf(g_n[1][b*L_ + tc*2 + 32*q    ], EPSF);
            dr[2*q+1] = fmaxf(g_n[1][b*L_ + tc*2 + 32*q + 1], EPSF);
        }
        #pragma unroll
        for (int r = 0; r < 8; r++)
            #pragma unroll
            for (int cc = 0; cc < 8; cc++)
                val[r][cc] /= (dl[r] * dr[cc]);
    }

    float rm[8], cmk[8];
    #pragma unroll
    for (int r = 0; r < 8; r++) rm[r] = mA[tr*8 + r];
    #pragma unroll
    for (int q = 0; q < 4; q++) {
        cmk[2*q]   = mB[tc*2 + 32*q];
        cmk[2*q+1] = mB[tc*2 + 32*q + 1];
    }
    float cnt2 = fmaxf((float)g_len[1][b], EPSF);
    float cnt1 = fmaxf((float)g_len[0][b], EPSF);

    if (!wt) {
        #pragma unroll
        for (int r = 0; r < 8; r++) {
            float* dst = g_Scos + ((size_t)(b*L_ + tr*8 + r)) * L_;
            #pragma unroll
            for (int q = 0; q < 4; q++)
                *(float2*)(dst + tc*2 + 32*q) = make_float2(val[r][2*q], val[r][2*q+1]);
        }
    }

    #pragma unroll
    for (int r = 0; r < 8; r++) {
        float mx = NEGINF, sm = 0.f;
        #pragma unroll
        for (int cc = 0; cc < 8; cc++)
            if (cmk[cc] != 0.f) { mx = fmaxf(mx, val[r][cc]); sm += val[r][cc]; }
        #pragma unroll
        for (int o = 8; o; o >>= 1) {
            mx = fmaxf(mx, __shfl_xor_sync(0xffffffffu, mx, o));
            sm += __shfl_xor_sync(0xffffffffu, sm, o);
        }
        if (tc == 0) {
            int i = tr*8 + r;
            float* o_ = out + ((size_t)(b*2 + 0)*L_ + i) * OUTD;
            float mean = sm / cnt2;
            if (!wt) { o_[0] = mx; o_[1] = mean; }
            else     { o_[36 + p] = mx; o_[52 + p] = mean; }
        }
    }

    float cmx[8], csm[8];
    #pragma unroll
    for (int cc = 0; cc < 8; cc++) { cmx[cc] = NEGINF; csm[cc] = 0.f; }
    #pragma unroll
    for (int r = 0; r < 8; r++)
        if (rm[r] != 0.f)
            #pragma unroll
            for (int cc = 0; cc < 8; cc++) {
                cmx[cc] = fmaxf(cmx[cc], val[r][cc]);
                csm[cc] += val[r][cc];
            }

    #pragma unroll
    for (int q = 0; q < 4; q++) {
        red[tr][tc*2 + 32*q]     = cmx[2*q];
        red[tr][tc*2 + 32*q + 1] = cmx[2*q+1];
    }
    __syncthreads();
    float fmx = NEGINF;
    if (tid < 128) {
        fmx = red[0][tid];
        #pragma unroll
        for (int t = 1; t < 16; t++) fmx = fmaxf(fmx, red[t][tid]);
    }
    __syncthreads();
    #pragma unroll
    for (int q = 0; q < 4; q++) {
        red[tr][tc*2 + 32*q]     = csm[2*q];
        red[tr][tc*2 + 32*q + 1] = csm[2*q+1];
    }
    __syncthreads();
    if (tid < 128) {
        float fsm = 0.f;
        #pragma unroll
        for (int t = 0; t < 16; t++) fsm += red[t][tid];
        float* o_ = out + ((size_t)(b*2 + 1)*L_ + tid) * OUTD;
        float mean = fsm / cnt1;
        if (!wt) { o_[0] = fmx; o_[1] = mean; }
        else     { o_[36 + p] = fmx; o_[52 + p] = mean; }
    }
}

// ---------------- attention sums/maxes + fused softmax (packed f32x2) ----------------
// grid (L/TT=8, B, 2) = 128 blocks, exactly 1/SM; depth-4 prefetched C stream.
#define ATT_BODY(CC, U) do {                                              \
    unsigned int _ub = cw_b + (unsigned int)((U) << 3);                   \
    _Pragma("unroll")                                                     \
    for (int tt = 0; tt < TT; tt++) {                                     \
        ull ww = lds64(_ub + (unsigned int)(tt * (L_*8)));                \
        ull pp; MUL2(pp, ww, (CC));                                       \
        FMA2(sm2[tt], ww, (CC));                                          \
        float pl, ph; UNPK2(pl, ph, pp);                                  \
        mxl[tt] = fmaxf(mxl[tt], pl);                                     \
        mxh[tt] = fmaxf(mxh[tt], ph);                                     \
    }                                                                     \
} while (0)

__global__ __launch_bounds__(ATT_THR) void k_att(
    const float* __restrict__ m1, const float* __restrict__ m2)
{
    int tb = blockIdx.x, b = blockIdx.y, s = blockIdx.z;
    int other = 1 - s;
    int lenO = g_len[other][b];           // always >= 64
    const float* C = g_c[other] + (size_t)b * L_ * H_;
    const float* Scos = g_Scos + (size_t)b * L_ * L_;
    const float* mkS = s ? m2 : m1;
    __shared__ __align__(16) ull cw2[TT][L_];       // {w,w} duplicated pairs
    __shared__ float rmx[TT][ATT_W], rsm[TT][ATT_W];
    int tid = threadIdx.x;
    for (int idx = tid; idx < TT*L_; idx += ATT_THR) {
        int tt = idx >> 7, u = idx & (L_-1);
        int t = tb*TT + tt;
        float w = (s == 0) ? Scos[(size_t)t * L_ + u] : Scos[(size_t)u * L_ + t];
        ull ww; PACK2(ww, w);
        cw2[tt][u] = ww;
    }
    __syncthreads();

    unsigned int cw_b = (unsigned int)__cvta_generic_to_shared(&cw2[0][0]);
    ull sm2[TT];
    float mxl[TT], mxh[TT];
    #pragma unroll
    for (int tt = 0; tt < TT; tt++) { sm2[tt] = 0ull; mxl[tt] = NEGINF; mxh[tt] = NEGINF; }

    const float* Cp = C + 2*tid;
    // depth-4 prefetch ring (rows beyond lenO are zero-masked but valid; clamp to L_-1)
    ull c0 = ldg64(Cp);
    ull c1 = ldg64(Cp + H_);
    ull c2 = ldg64(Cp + 2*H_);
    ull c3 = ldg64(Cp + 3*H_);
    int u = 0;
    for (; u + 4 <= lenO; u += 4) {
        int n0 = u+4 < L_ ? u+4 : L_-1;
        int n1 = u+5 < L_ ? u+5 : L_-1;
        int n2 = u+6 < L_ ? u+6 : L_-1;
        int n3 = u+7 < L_ ? u+7 : L_-1;
        ATT_BODY(c0, u);     c0 = ldg64(Cp + (size_t)n0 * H_);
        ATT_BODY(c1, u+1);   c1 = ldg64(Cp + (size_t)n1 * H_);
        ATT_BODY(c2, u+2);   c2 = ldg64(Cp + (size_t)n2 * H_);
        ATT_BODY(c3, u+3);   c3 = ldg64(Cp + (size_t)n3 * H_);
    }
    if (u < lenO) { ATT_BODY(c0, u); u++; }
    if (u < lenO) { ATT_BODY(c1, u); u++; }
    if (u < lenO) { ATT_BODY(c2, u); u++; }

    int w = tid >> 5, lane = tid & 31;
    // store maxes
    #pragma unroll
    for (int tt = 0; tt < TT; tt++) {
        int t = tb*TT + tt;
        size_t base = ((size_t)(b*L_ + t)) * H_;
        *(float2*)(&g_attM[s][base + 2*tid]) = make_float2(mxl[tt], mxh[tt]);
    }

    // fused softmax: stage per-warp partial maxes for all tokens, one sync
    float s0[TT], s1[TT];
    #pragma unroll
    for (int tt = 0; tt < TT; tt++) {
        UNPK2(s0[tt], s1[tt], sm2[tt]);
        float lm = fmaxf(s0[tt], s1[tt]);
        #pragma unroll
        for (int o = 16; o; o >>= 1) lm = fmaxf(lm, __shfl_xor_sync(0xffffffffu, lm, o));
        if (lane == 0) rmx[tt][w] = lm;
    }
    __syncthreads();
    float bm[TT];
    #pragma unroll
    for (int tt = 0; tt < TT; tt++) {
        float m = rmx[tt][0];
        #pragma unroll
        for (int i = 1; i < ATT_W; i++) m = fmaxf(m, rmx[tt][i]);
        bm[tt] = m;
    }
    float e0[TT], e1[TT];
    #pragma unroll
    for (int tt = 0; tt < TT; tt++) {
        e0[tt] = expf(s0[tt] - bm[tt]);
        e1[tt] = expf(s1[tt] - bm[tt]);
        float ls = e0[tt] + e1[tt];
        #pragma unroll
        for (int o = 16; o; o >>= 1) ls += __shfl_xor_sync(0xffffffffu, ls, o);
        if (lane == 0) rsm[tt][w] = ls;
    }
    __syncthreads();
    #pragma unroll
    for (int tt = 0; tt < TT; tt++) {
        int t = tb*TT + tt;
        size_t base = ((size_t)(b*L_ + t)) * H_;
        float m = mkS[b*L_ + t];
        if (m == 0.f) {
            *(float2*)(&g_attS[s][base + 2*tid]) = make_float2(1.f/(float)H_, 1.f/(float)H_);
            continue;
        }
        float bs = 0.f;
        #pragma unroll
        for (int i = 0; i < ATT_W; i++) bs += rsm[tt][i];
        float inv = 1.f / bs;
        *(float2*)(&g_attS[s][base + 2*tid]) = make_float2(e0[tt]*inv, e1[tt]*inv);
    }
}

// ---------------- per-token weighted cosines (packed f32x2) ----------------
__global__ __launch_bounds__(256) void k_final(
    const float* __restrict__ wff, const float* __restrict__ wfb,
    const float* __restrict__ watt, const float* __restrict__ wmatt,
    float* __restrict__ out)
{
    int t = blockIdx.x, b = blockIdx.y, s = blockIdx.z;
    int other = 1 - s;
    __shared__ __align__(16) float sa[H_];
    __shared__ __align__(16) float sv[4][H_];
    int tid = threadIdx.x;
    const float* a = g_c[s] + ((size_t)(b*L_ + t)) * H_;
    int lenO = g_len[other][b];
    int lp = lenO > 0 ? lenO - 1 : 0;
    const float* v_ff  = g_c[other] + ((size_t)(b*L_ + lp)) * H_;
    const float* v_bf  = g_c[other] + ((size_t)(b*L_)) * H_;
    const float* v_am  = g_attS[s] + ((size_t)(b*L_ + t)) * H_;
    const float* v_amx = g_attM[s] + ((size_t)(b*L_ + t)) * H_;
    for (int h = tid; h < H_; h += 256) {
        sa[h] = a[h];
        sv[0][h] = v_ff[h];
        sv[1][h] = v_bf[h];
        sv[2][h] = v_am[h];
        sv[3][h] = v_amx[h];
    }
    __syncthreads();

    unsigned int sa_b = (unsigned int)__cvta_generic_to_shared(sa);
    unsigned int sv_b = (unsigned int)__cvta_generic_to_shared(&sv[0][0]);
    int w = tid >> 5, lane = tid & 31;
    float* o_ = out + ((size_t)(b*2 + s)*L_ + t) * OUTD;
    for (int task = w; task < 68; task += 8) {
        int q = task / 17;
        int tt = task - q * 17;
        const float* W = (q == 0) ? wff : (q == 1) ? wfb : (q == 2) ? watt : wmatt;
        int base = (q == 0) ? 2 : (q == 1) ? 19 : (q == 2) ? 68 : 85;
        const float* Wr = W + tt * H_;
        unsigned int svq = sv_b + (unsigned int)(q * H_ * 4);
        ull sav = 0ull, saa = 0ull, svv = 0ull;
        if (tt < P_) {
            #pragma unroll
            for (int k = 0; k < 12; k++) {
                int h2 = (lane + (k << 5)) << 1;
                ull a2 = lds64(sa_b + (unsigned int)(h2 << 2));
                ull v2 = lds64(svq  + (unsigned int)(h2 << 2));
                ull w2 = ldg64(Wr + h2);
                MUL2(a2, a2, w2);
                MUL2(v2, v2, w2);
                FMA2(sav, a2, v2);
                FMA2(saa, a2, a2);
                FMA2(svv, v2, v2);
            }
        } else {
            #pragma unroll
            for (int k = 0; k < 12; k++) {
                int h2 = (lane + (k << 5)) << 1;
                ull a2 = lds64(sa_b + (unsigned int)(h2 << 2));
                ull v2 = lds64(svq  + (unsigned int)(h2 << 2));
                FMA2(sav, a2, v2);
                FMA2(saa, a2, a2);
                FMA2(svv, v2, v2);
            }
        }
        float lo, hi, fsav, fsaa, fsvv;
        UNPK2(lo, hi, sav); fsav = lo + hi;
        UNPK2(lo, hi, saa); fsaa = lo + hi;
        UNPK2(lo, hi, svv); fsvv = lo + hi;
        #pragma unroll
        for (int o = 16; o; o >>= 1) {
            fsav += __shfl_xor_sync(0xffffffffu, fsav, o);
            fsaa += __shfl_xor_sync(0xffffffffu, fsaa, o);
            fsvv += __shfl_xor_sync(0xffffffffu, fsvv, o);
        }
        if (lane == 0) {
            float na = fmaxf(sqrtf(fsaa), EPSF);
            float nv = fmaxf(sqrtf(fsvv), EPSF);
            int col = (tt == P_) ? base : (base + 1 + tt);
            o_[col] = fsav / (na * nv);
        }
    }
}

// ---------------- launch ----------------
extern "C" void kernel_launch(void* const* d_in, const int* in_sizes, int n_in,
                              void* d_out, int out_size) {
    const float* c1    = (const float*)d_in[0];
    const float* m1    = (const float*)d_in[1];
    const float* c2    = (const float*)d_in[2];
    const float* m2    = (const float*)d_in[3];
    const float* wff   = (const float*)d_in[4];
    const float* wfb   = (const float*)d_in[5];
    const float* wmp   = (const float*)d_in[6];
    const float* watt  = (const float*)d_in[7];
    const float* wmatt = (const float*)d_in[8];
    float* out = (float*)d_out;
    (void)in_sizes; (void)n_in; (void)out_size;

    k_len    <<<1, 64>>>(m1, m2);
    k_prep   <<<dim3(L_, B_, 2), 256>>>(c1, m1, c2, m2, wmp);
    k_gemm   <<<dim3(NCH, B_), 256>>>(wmp, m1, m2, out);
    k_att    <<<dim3(L_/TT, B_, 2), ATT_THR>>>(m1, m2);
    k_final  <<<dim3(L_, B_, 2), 256>>>(wff, wfb, watt, wmatt, out);
}

// round 12
// speedup vs baseline: 1.2360x; 1.0108x over previous
#include <cuda_runtime.h>
#include <math.h>

typedef unsigned long long ull;

// Problem constants (fixed by reference setup_inputs)
#define B_  8
#define L_  128
#define H_  768
#define P_  16
#define OUTD 102
#define EPSF 1e-8f
#define NEGINF (-1e30f)
#define TT 16           // token tile for attention kernel (128 blocks, 1/SM)
#define ATT_THR 384     // 384 threads = 768 h / 2 packed
#define ATT_W   12      // warps per att block

// ---------------- scratch (static device memory; no allocation) ----------------
__device__ float g_c[2][B_*L_*H_];      // masked contexts
__device__ float g_n[2][B_*L_];         // plain L2 norms
__device__ float g_nw[2][B_*L_*P_];     // w_mp-weighted norms
__device__ float g_Scos[B_*L_*L_];      // cosine channel (for k_att)
__device__ float g_attS[2][B_*L_*H_];   // att softmax (att_mean)
__device__ float g_attM[2][B_*L_*H_];   // att maxes
__device__ int   g_len[2][B_];

// ---------------- packed fp32x2 helpers ----------------
#define FMA2(d,a,b)    asm("fma.rn.f32x2 %0, %1, %2, %0;" : "+l"(d) : "l"(a), "l"(b))
#define MUL2(d,a,b)    asm("mul.rn.f32x2 %0, %1, %2;" : "=l"(d) : "l"(a), "l"(b))
#define PACK2(d,x)     asm("mov.b64 %0, {%1, %2};" : "=l"(d) : "f"(x), "f"(x))
#define UNPK2(lo,hi,v) asm("mov.b64 {%0, %1}, %2;" : "=f"(lo), "=f"(hi) : "l"(v))

__device__ __forceinline__ ull lds64(unsigned int addr) {
    ull v; asm volatile("ld.shared.b64 %0, [%1];" : "=l"(v) : "r"(addr)); return v;
}
__device__ __forceinline__ ull ldg64(const float* p) {
    ull v; asm volatile("ld.global.nc.b64 %0, [%1];" : "=l"(v) : "l"(p)); return v;
}

// ---------------- lengths ----------------
__global__ void k_len(const float* __restrict__ m1, const float* __restrict__ m2) {
    int t = threadIdx.x;
    if (t < 16) {
        int s = t >> 3, b = t & 7;
        const float* mk = s ? m2 : m1;
        float acc = 0.f;
        for (int j = 0; j < L_; j++) acc += mk[b*L_ + j];
        g_len[s][b] = (int)(acc + 0.5f);
    }
}

// ---------------- masked context + norms ----------------
__global__ __launch_bounds__(256) void k_prep(
    const float* __restrict__ ctx1, const float* __restrict__ m1,
    const float* __restrict__ ctx2, const float* __restrict__ m2,
    const float* __restrict__ w_mp)
{
    int i = blockIdx.x, b = blockIdx.y, s = blockIdx.z;
    const float* ctx = s ? ctx2 : ctx1;
    const float* mk  = s ? m2   : m1;
    __shared__ float cs[H_];
    float m = mk[b*L_ + i];
    int tid = threadIdx.x;
    float* cdst = g_c[s] + (size_t)(b*L_ + i) * H_;
    const float* csrc = ctx + (size_t)(b*L_ + i) * H_;
    for (int h = tid; h < H_; h += 256) {
        float v = csrc[h] * m;
        cs[h] = v;
        cdst[h] = v;
    }
    __syncthreads();
    int w = tid >> 5, lane = tid & 31;
    for (int t = w; t < P_ + 1; t += 8) {
        float acc = 0.f;
        #pragma unroll
        for (int k = 0; k < H_/32; k++) {
            int h = lane + 32*k;
            float c = cs[h];
            float x = (t < P_) ? w_mp[t*H_ + h] * c : c;
            acc = fmaf(x, x, acc);
        }
        #pragma unroll
        for (int o = 16; o; o >>= 1) acc += __shfl_xor_sync(0xffffffffu, acc, o);
        if (lane == 0) {
            if (t == P_) g_n[s][b*L_ + i] = sqrtf(acc);
            else         g_nw[s][(b*L_ + i)*P_ + t] = sqrtf(acc);
        }
    }
}

// ---------------- 16-channel WEIGHTED pairwise GEMM + masked reductions ----------------
// grid (P_, B): one 128x128 tile per block (channel p), stats -> out cols 36..67
__global__ __launch_bounds__(256) void k_gemm(
    const float* __restrict__ w_mp,
    const float* __restrict__ m1, const float* __restrict__ m2,
    float* __restrict__ out)
{
    int p = blockIdx.x, b = blockIdx.y;
    const float* A  = g_c[0] + (size_t)b * L_ * H_;
    const float* Bm = g_c[1] + (size_t)b * L_ * H_;
    __shared__ __align__(16) float As[16][128];
    __shared__ __align__(16) float Bs[16][128];
    __shared__ float mA[L_], mB[L_];
    __shared__ float red[16][132];
    int tid = threadIdx.x;
    if (tid < 128) mA[tid] = m1[b*L_ + tid];
    else           mB[tid-128] = m2[b*L_ + tid - 128];

    int lr = tid & 127, lk = (tid >> 7) << 3;
    int tr = tid >> 4,  tc = tid & 15;
    const float* wp = w_mp + p * H_;

    ull acc[8][4];
    #pragma unroll
    for (int r = 0; r < 8; r++)
        #pragma unroll
        for (int q = 0; q < 4; q++) acc[r][q] = 0ull;

    unsigned int bs_b = (unsigned int)__cvta_generic_to_shared(&Bs[0][0]);

    float4 pa0, pa1, pb0, pb1;
    {
        const float* Ap = A  + (size_t)lr * H_ + lk;
        const float* Bp = Bm + (size_t)lr * H_ + lk;
        pa0 = *(const float4*)(Ap);     pa1 = *(const float4*)(Ap + 4);
        pb0 = *(const float4*)(Bp);     pb1 = *(const float4*)(Bp + 4);
        float4 w0 = *(const float4*)(wp + lk);
        float4 w1 = *(const float4*)(wp + lk + 4);
        pa0.x*=w0.x; pa0.y*=w0.y; pa0.z*=w0.z; pa0.w*=w0.w;
        pa1.x*=w1.x; pa1.y*=w1.y; pa1.z*=w1.z; pa1.w*=w1.w;
        pb0.x*=w0.x; pb0.y*=w0.y; pb0.z*=w0.z; pb0.w*=w0.w;
        pb1.x*=w1.x; pb1.y*=w1.y; pb1.z*=w1.z; pb1.w*=w1.w;
    }

    for (int c = 0; c < H_/16; c++) {
        As[lk+0][lr]=pa0.x; As[lk+1][lr]=pa0.y; As[lk+2][lr]=pa0.z; As[lk+3][lr]=pa0.w;
        As[lk+4][lr]=pa1.x; As[lk+5][lr]=pa1.y; As[lk+6][lr]=pa1.z; As[lk+7][lr]=pa1.w;
        Bs[lk+0][lr]=pb0.x; Bs[lk+1][lr]=pb0.y; Bs[lk+2][lr]=pb0.z; Bs[lk+3][lr]=pb0.w;
        Bs[lk+4][lr]=pb1.x; Bs[lk+5][lr]=pb1.y; Bs[lk+6][lr]=pb1.z; Bs[lk+7][lr]=pb1.w;
        __syncthreads();
        if (c + 1 < H_/16) {
            int k0 = (c + 1) * 16;
            const float* Ap = A  + (size_t)lr * H_ + k0 + lk;
            const float* Bp = Bm + (size_t)lr * H_ + k0 + lk;
            pa0 = *(const float4*)(Ap);     pa1 = *(const float4*)(Ap + 4);
            pb0 = *(const float4*)(Bp);     pb1 = *(const float4*)(Bp + 4);
            float4 w0 = *(const float4*)(wp + k0 + lk);
            float4 w1 = *(const float4*)(wp + k0 + lk + 4);
            pa0.x*=w0.x; pa0.y*=w0.y; pa0.z*=w0.z; pa0.w*=w0.w;
            pa1.x*=w1.x; pa1.y*=w1.y; pa1.z*=w1.z; pa1.w*=w1.w;
            pb0.x*=w0.x; pb0.y*=w0.y; pb0.z*=w0.z; pb0.w*=w0.w;
            pb1.x*=w1.x; pb1.y*=w1.y; pb1.z*=w1.z; pb1.w*=w1.w;
        }
        #pragma unroll
        for (int k = 0; k < 16; k++) {
            float4 ra0 = *(const float4*)&As[k][tr << 3];
            float4 ra1 = *(const float4*)&As[k][(tr << 3) + 4];
            unsigned int bb = bs_b + (unsigned int)((((k << 7) + (tc << 1))) << 2);
            ull b0 = lds64(bb);
            ull b1 = lds64(bb + 32*4);
            ull b2 = lds64(bb + 64*4);
            ull b3 = lds64(bb + 96*4);
            float av[8] = {ra0.x, ra0.y, ra0.z, ra0.w, ra1.x, ra1.y, ra1.z, ra1.w};
            #pragma unroll
            for (int r = 0; r < 8; r++) {
                ull aa; PACK2(aa, av[r]);
                FMA2(acc[r][0], aa, b0);
                FMA2(acc[r][1], aa, b1);
                FMA2(acc[r][2], aa, b2);
                FMA2(acc[r][3], aa, b3);
            }
        }
        __syncthreads();
    }

    float val[8][8];
    #pragma unroll
    for (int r = 0; r < 8; r++)
        #pragma unroll
        for (int q = 0; q < 4; q++)
            UNPK2(val[r][2*q], val[r][2*q+1], acc[r][q]);

    {
        float dl[8], dr[8];
        #pragma unroll
        for (int r = 0; r < 8; r++) dl[r] = g_nw[0][(b*L_ + (tr*8 + r))*P_ + p];
        #pragma unroll
        for (int q = 0; q < 4; q++) {
            dr[2*q]   = g_nw[1][(b*L_ + tc*2 + 32*q    )*P_ + p];
            dr[2*q+1] = g_nw[1][(b*L_ + tc*2 + 32*q + 1)*P_ + p];
        }
        #pragma unroll
        for (int r = 0; r < 8; r++)
            #pragma unroll
            for (int cc = 0; cc < 8; cc++)
                val[r][cc] /= fmaxf(dl[r] * dr[cc], EPSF);   // clip PRODUCT (ref)
    }

    float rm[8], cmk[8];
    #pragma unroll
    for (int r = 0; r < 8; r++) rm[r] = mA[tr*8 + r];
    #pragma unroll
    for (int q = 0; q < 4; q++) {
        cmk[2*q]   = mB[tc*2 + 32*q];
        cmk[2*q+1] = mB[tc*2 + 32*q + 1];
    }
    float cnt2 = fmaxf((float)g_len[1][b], EPSF);
    float cnt1 = fmaxf((float)g_len[0][b], EPSF);

    // row reductions (over j, mask_2)
    #pragma unroll
    for (int r = 0; r < 8; r++) {
        float mx = NEGINF, sm = 0.f;
        #pragma unroll
        for (int cc = 0; cc < 8; cc++)
            if (cmk[cc] != 0.f) { mx = fmaxf(mx, val[r][cc]); sm += val[r][cc]; }
        #pragma unroll
        for (int o = 8; o; o >>= 1) {
            mx = fmaxf(mx, __shfl_xor_sync(0xffffffffu, mx, o));
            sm += __shfl_xor_sync(0xffffffffu, sm, o);
        }
        if (tc == 0) {
            int i = tr*8 + r;
            float* o_ = out + ((size_t)(b*2 + 0)*L_ + i) * OUTD;
            o_[36 + p] = mx; o_[52 + p] = sm / cnt2;
        }
    }

    // col reductions (over i, mask_1)
    float cmx[8], csm[8];
    #pragma unroll
    for (int cc = 0; cc < 8; cc++) { cmx[cc] = NEGINF; csm[cc] = 0.f; }
    #pragma unroll
    for (int r = 0; r < 8; r++)
        if (rm[r] != 0.f)
            #pragma unroll
            for (int cc = 0; cc < 8; cc++) {
                cmx[cc] = fmaxf(cmx[cc], val[r][cc]);
                csm[cc] += val[r][cc];
            }
    #pragma unroll
    for (int q = 0; q < 4; q++) {
        red[tr][tc*2 + 32*q]     = cmx[2*q];
        red[tr][tc*2 + 32*q + 1] = cmx[2*q+1];
    }
    __syncthreads();
    float fmx = NEGINF;
    if (tid < 128) {
        fmx = red[0][tid];
        #pragma unroll
        for (int t = 1; t < 16; t++) fmx = fmaxf(fmx, red[t][tid]);
    }
    __syncthreads();
    #pragma unroll
    for (int q = 0; q < 4; q++) {
        red[tr][tc*2 + 32*q]     = csm[2*q];
        red[tr][tc*2 + 32*q + 1] = csm[2*q+1];
    }
    __syncthreads();
    if (tid < 128) {
        float fsm = 0.f;
        #pragma unroll
        for (int t = 0; t < 16; t++) fsm += red[t][tid];
        float* o_ = out + ((size_t)(b*2 + 1)*L_ + tid) * OUTD;
        o_[36 + p] = fmx; o_[52 + p] = fsm / cnt1;
    }
}

// ---------------- cosine channel GEMM (32-row stripes, grid (4,B)) ----------------
__global__ __launch_bounds__(256) void k_gcos() {
    int b = blockIdx.y;
    int r0 = blockIdx.x * 32;
    const float* A  = g_c[0] + (size_t)b * L_ * H_ + (size_t)r0 * H_;
    const float* Bm = g_c[1] + (size_t)b * L_ * H_;
    __shared__ __align__(16) float As[16][32];
    __shared__ __align__(16) float Bs[16][128];
    int tid = threadIdx.x;
    int ar = tid >> 2, ak = (tid & 3) << 2;          // A loader (tid<128): row 0..31
    int br = tid & 127, bk = (tid >> 7) << 3;        // B loader: row 0..127
    int tr = tid >> 4,  tc = tid & 15;               // compute: 2 rows (tr*2+), 8 cols

    ull acc[2][4];
    #pragma unroll
    for (int r = 0; r < 2; r++)
        #pragma unroll
        for (int q = 0; q < 4; q++) acc[r][q] = 0ull;

    unsigned int bs_b = (unsigned int)__cvta_generic_to_shared(&Bs[0][0]);

    for (int c = 0; c < H_/16; c++) {
        int k0 = c * 16;
        float4 b4a = *(const float4*)(Bm + (size_t)br * H_ + k0 + bk);
        float4 b4b = *(const float4*)(Bm + (size_t)br * H_ + k0 + bk + 4);
        float4 a4;
        if (tid < 128) a4 = *(const float4*)(A + (size_t)ar * H_ + k0 + ak);
        __syncthreads();
        if (tid < 128) {
            As[ak+0][ar]=a4.x; As[ak+1][ar]=a4.y; As[ak+2][ar]=a4.z; As[ak+3][ar]=a4.w;
        }
        Bs[bk+0][br]=b4a.x; Bs[bk+1][br]=b4a.y; Bs[bk+2][br]=b4a.z; Bs[bk+3][br]=b4a.w;
        Bs[bk+4][br]=b4b.x; Bs[bk+5][br]=b4b.y; Bs[bk+6][br]=b4b.z; Bs[bk+7][br]=b4b.w;
        __syncthreads();
        #pragma unroll
        for (int k = 0; k < 16; k++) {
            float a0 = As[k][tr*2], a1 = As[k][tr*2 + 1];
            unsigned int bb = bs_b + (unsigned int)((((k << 7) + (tc << 1))) << 2);
            ull b0 = lds64(bb);
            ull b1 = lds64(bb + 32*4);
            ull b2 = lds64(bb + 64*4);
            ull b3 = lds64(bb + 96*4);
            ull aa0; PACK2(aa0, a0);
            ull aa1; PACK2(aa1, a1);
            FMA2(acc[0][0], aa0, b0); FMA2(acc[0][1], aa0, b1);
            FMA2(acc[0][2], aa0, b2); FMA2(acc[0][3], aa0, b3);
            FMA2(acc[1][0], aa1, b0); FMA2(acc[1][1], aa1, b1);
            FMA2(acc[1][2], aa1, b2); FMA2(acc[1][3], aa1, b3);
        }
    }

    float dl0 = fmaxf(g_n[0][b*L_ + r0 + tr*2],     EPSF);
    float dl1 = fmaxf(g_n[0][b*L_ + r0 + tr*2 + 1], EPSF);
    #pragma unroll
    for (int q = 0; q < 4; q++) {
        int col = tc*2 + 32*q;
        float drx = fmaxf(g_n[1][b*L_ + col    ], EPSF);
        float dry = fmaxf(g_n[1][b*L_ + col + 1], EPSF);
        float l0, h0, l1, h1;
        UNPK2(l0, h0, acc[0][q]);
        UNPK2(l1, h1, acc[1][q]);
        float* d0 = g_Scos + ((size_t)(b*L_ + r0 + tr*2    )) * L_ + col;
        float* d1 = g_Scos + ((size_t)(b*L_ + r0 + tr*2 + 1)) * L_ + col;
        *(float2*)d0 = make_float2(l0/(dl0*drx), h0/(dl0*dry));
        *(float2*)d1 = make_float2(l1/(dl1*drx), h1/(dl1*dry));
    }
}

// ---------------- attention sums/maxes + cos stats + fused softmax ----------------
#define ATT_BODY(CC, U) do {                                              \
    unsigned int _ub = cw_b + (unsigned int)((U) << 3);                   \
    _Pragma("unroll")                                                     \
    for (int tt = 0; tt < TT; tt++) {                                     \
        ull ww = lds64(_ub + (unsigned int)(tt * (L_*8)));                \
        ull pp; MUL2(pp, ww, (CC));                                       \
        FMA2(sm2[tt], ww, (CC));                                          \
        float pl, ph; UNPK2(pl, ph, pp);                                  \
        mxl[tt] = fmaxf(mxl[tt], pl);                                     \
        mxh[tt] = fmaxf(mxh[tt], ph);                                     \
    }                                                                     \
} while (0)

__global__ __launch_bounds__(ATT_THR) void k_att(
    const float* __restrict__ m1, const float* __restrict__ m2,
    float* __restrict__ out)
{
    int tb = blockIdx.x, b = blockIdx.y, s = blockIdx.z;
    int other = 1 - s;
    int lenO = g_len[other][b];           // always >= 64
    const float* C = g_c[other] + (size_t)b * L_ * H_;
    const float* Scos = g_Scos + (size_t)b * L_ * L_;
    const float* mkS = s ? m2 : m1;
    const float* mkO = s ? m1 : m2;       // mask over the reduced axis u
    __shared__ __align__(16) ull cw2[TT][L_];       // {w,w} duplicated pairs
    __shared__ float rmx[TT][ATT_W], rsm[TT][ATT_W];
    int tid = threadIdx.x;
    for (int idx = tid; idx < TT*L_; idx += ATT_THR) {
        int tt = idx >> 7, u = idx & (L_-1);
        int t = tb*TT + tt;
        float w = (s == 0) ? Scos[(size_t)t * L_ + u] : Scos[(size_t)u * L_ + t];
        ull ww; PACK2(ww, w);
        cw2[tt][u] = ww;
    }
    __syncthreads();

    int w = tid >> 5, lane = tid & 31;

    // cosine-channel masked max/mean over u  ->  out cols 0,1
    for (int tt = w; tt < TT; tt += ATT_W) {
        int t = tb*TT + tt;
        float mx = NEGINF, sm = 0.f;
        #pragma unroll
        for (int k4 = 0; k4 < 4; k4++) {
            int u = lane + (k4 << 5);
            float v = ((const float*)&cw2[tt][u])[0];
            if (mkO[b*L_ + u] != 0.f) { mx = fmaxf(mx, v); sm += v; }
        }
        #pragma unroll
        for (int o = 16; o; o >>= 1) {
            mx = fmaxf(mx, __shfl_xor_sync(0xffffffffu, mx, o));
            sm += __shfl_xor_sync(0xffffffffu, sm, o);
        }
        if (lane == 0) {
            float* o_ = out + ((size_t)(b*2 + s)*L_ + t) * OUTD;
            o_[0] = mx;
            o_[1] = sm / fmaxf((float)lenO, EPSF);
        }
    }

    unsigned int cw_b = (unsigned int)__cvta_generic_to_shared(&cw2[0][0]);
    ull sm2[TT];
    float mxl[TT], mxh[TT];
    #pragma unroll
    for (int tt = 0; tt < TT; tt++) { sm2[tt] = 0ull; mxl[tt] = NEGINF; mxh[tt] = NEGINF; }

    const float* Cp = C + 2*tid;
    // depth-4 prefetch ring (rows beyond lenO are zero-masked but valid; clamp to L_-1)
    ull c0 = ldg64(Cp);
    ull c1 = ldg64(Cp + H_);
    ull c2 = ldg64(Cp + 2*H_);
    ull c3 = ldg64(Cp + 3*H_);
    int u = 0;
    for (; u + 4 <= lenO; u += 4) {
        int n0 = u+4 < L_ ? u+4 : L_-1;
        int n1 = u+5 < L_ ? u+5 : L_-1;
        int n2 = u+6 < L_ ? u+6 : L_-1;
        int n3 = u+7 < L_ ? u+7 : L_-1;
        ATT_BODY(c0, u);     c0 = ldg64(Cp + (size_t)n0 * H_);
        ATT_BODY(c1, u+1);   c1 = ldg64(Cp + (size_t)n1 * H_);
        ATT_BODY(c2, u+2);   c2 = ldg64(Cp + (size_t)n2 * H_);
        ATT_BODY(c3, u+3);   c3 = ldg64(Cp + (size_t)n3 * H_);
    }
    if (u < lenO) { ATT_BODY(c0, u); u++; }
    if (u < lenO) { ATT_BODY(c1, u); u++; }
    if (u < lenO) { ATT_BODY(c2, u); u++; }

    // store maxes
    #pragma unroll
    for (int tt = 0; tt < TT; tt++) {
        int t = tb*TT + tt;
        size_t base = ((size_t)(b*L_ + t)) * H_;
        *(float2*)(&g_attM[s][base + 2*tid]) = make_float2(mxl[tt], mxh[tt]);
    }

    // fused softmax: stage per-warp partial maxes for all tokens, one sync
    float s0[TT], s1[TT];
    #pragma unroll
    for (int tt = 0; tt < TT; tt++) {
        UNPK2(s0[tt], s1[tt], sm2[tt]);
        float lm = fmaxf(s0[tt], s1[tt]);
        #pragma unroll
        for (int o = 16; o; o >>= 1) lm = fmaxf(lm, __shfl_xor_sync(0xffffffffu, lm, o));
        if (lane == 0) rmx[tt][w] = lm;
    }
    __syncthreads();
    float bm[TT];
    #pragma unroll
    for (int tt = 0; tt < TT; tt++) {
        float m = rmx[tt][0];
        #pragma unroll
        for (int i = 1; i < ATT_W; i++) m = fmaxf(m, rmx[tt][i]);
        bm[tt] = m;
    }
    float e0[TT], e1[TT];
    #pragma unroll
    for (int tt = 0; tt < TT; tt++) {
        e0[tt] = expf(s0[tt] - bm[tt]);
        e1[tt] = expf(s1[tt] - bm[tt]);
        float ls = e0[tt] + e1[tt];
        #pragma unroll
        for (int o = 16; o; o >>= 1) ls += __shfl_xor_sync(0xffffffffu, ls, o);
        if (lane == 0) rsm[tt][w] = ls;
    }
    __syncthreads();
    #pragma unroll
    for (int tt = 0; tt < TT; tt++) {
        int t = tb*TT + tt;
        size_t base = ((size_t)(b*L_ + t)) * H_;
        float m = mkS[b*L_ + t];
        if (m == 0.f) {
            *(float2*)(&g_attS[s][base + 2*tid]) = make_float2(1.f/(float)H_, 1.f/(float)H_);
            continue;
        }
        float bs = 0.f;
        #pragma unroll
        for (int i = 0; i < ATT_W; i++) bs += rsm[tt][i];
        float inv = 1.f / bs;
        *(float2*)(&g_attS[s][base + 2*tid]) = make_float2(e0[tt]*inv, e1[tt]*inv);
    }
}

// ---------------- per-token weighted cosines (packed f32x2) ----------------
__global__ __launch_bounds__(256) void k_final(
    const float* __restrict__ wff, const float* __restrict__ wfb,
    const float* __restrict__ watt, const float* __restrict__ wmatt,
    float* __restrict__ out)
{
    int t = blockIdx.x, b = blockIdx.y, s = blockIdx.z;
    int other = 1 - s;
    __shared__ __align__(16) float sa[H_];
    __shared__ __align__(16) float sv[4][H_];
    int tid = threadIdx.x;
    const float* a = g_c[s] + ((size_t)(b*L_ + t)) * H_;
    int lenO = g_len[other][b];
    int lp = lenO > 0 ? lenO - 1 : 0;
    const float* v_ff  = g_c[other] + ((size_t)(b*L_ + lp)) * H_;
    const float* v_bf  = g_c[other] + ((size_t)(b*L_)) * H_;
    const float* v_am  = g_attS[s] + ((size_t)(b*L_ + t)) * H_;
    const float* v_amx = g_attM[s] + ((size_t)(b*L_ + t)) * H_;
    for (int h = tid; h < H_; h += 256) {
        sa[h] = a[h];
        sv[0][h] = v_ff[h];
        sv[1][h] = v_bf[h];
        sv[2][h] = v_am[h];
        sv[3][h] = v_amx[h];
    }
    __syncthreads();

    unsigned int sa_b = (unsigned int)__cvta_generic_to_shared(sa);
    unsigned int sv_b = (unsigned int)__cvta_generic_to_shared(&sv[0][0]);
    int w = tid >> 5, lane = tid & 31;
    float* o_ = out + ((size_t)(b*2 + s)*L_ + t) * OUTD;
    for (int task = w; task < 68; task += 8) {
        int q = task / 17;
        int tt = task - q * 17;
        const float* W = (q == 0) ? wff : (q == 1) ? wfb : (q == 2) ? watt : wmatt;
        int base = (q == 0) ? 2 : (q == 1) ? 19 : (q == 2) ? 68 : 85;
        const float* Wr = W + tt * H_;
        unsigned int svq = sv_b + (unsigned int)(q * H_ * 4);
        ull sav = 0ull, saa = 0ull, svv = 0ull;
        if (tt < P_) {
            #pragma unroll
            for (int k = 0; k < 12; k++) {
                int h2 = (lane + (k << 5)) << 1;
                ull a2 = lds64(sa_b + (unsigned int)(h2 << 2));
                ull v2 = lds64(svq  + (unsigned int)(h2 << 2));
                ull w2 = ldg64(Wr + h2);
                MUL2(a2, a2, w2);
                MUL2(v2, v2, w2);
                FMA2(sav, a2, v2);
                FMA2(saa, a2, a2);
                FMA2(svv, v2, v2);
            }
        } else {
            #pragma unroll
            for (int k = 0; k < 12; k++) {
                int h2 = (lane + (k << 5)) << 1;
                ull a2 = lds64(sa_b + (unsigned int)(h2 << 2));
                ull v2 = lds64(svq  + (unsigned int)(h2 << 2));
                FMA2(sav, a2, v2);
                FMA2(saa, a2, a2);
                FMA2(svv, v2, v2);
            }
        }
        float lo, hi, fsav, fsaa, fsvv;
        UNPK2(lo, hi, sav); fsav = lo + hi;
        UNPK2(lo, hi, saa); fsaa = lo + hi;
        UNPK2(lo, hi, svv); fsvv = lo + hi;
        #pragma unroll
        for (int o = 16; o; o >>= 1) {
            fsav += __shfl_xor_sync(0xffffffffu, fsav, o);
            fsaa += __shfl_xor_sync(0xffffffffu, fsaa, o);
            fsvv += __shfl_xor_sync(0xffffffffu, fsvv, o);
        }
        if (lane == 0) {
            float na = fmaxf(sqrtf(fsaa), EPSF);
            float nv = fmaxf(sqrtf(fsvv), EPSF);
            int col = (tt == P_) ? base : (base + 1 + tt);
            o_[col] = fsav / (na * nv);
        }
    }
}

// ---------------- launch (fork weighted GEMM onto a side stream) ----------------
extern "C" void kernel_launch(void* const* d_in, const int* in_sizes, int n_in,
                              void* d_out, int out_size) {
    const float* c1    = (const float*)d_in[0];
    const float* m1    = (const float*)d_in[1];
    const float* c2    = (const float*)d_in[2];
    const float* m2    = (const float*)d_in[3];
    const float* wff   = (const float*)d_in[4];
    const float* wfb   = (const float*)d_in[5];
    const float* wmp   = (const float*)d_in[6];
    const float* watt  = (const float*)d_in[7];
    const float* wmatt = (const float*)d_in[8];
    float* out = (float*)d_out;
    (void)in_sizes; (void)n_in; (void)out_size;

    static cudaStream_t sB = nullptr;
    static cudaEvent_t evF = nullptr, evB = nullptr;
    if (!sB) {
        cudaStreamCreateWithFlags(&sB, cudaStreamNonBlocking);
        cudaEventCreateWithFlags(&evF, cudaEventDisableTiming);
        cudaEventCreateWithFlags(&evB, cudaEventDisableTiming);
    }

    k_len  <<<1, 64>>>(m1, m2);
    k_prep <<<dim3(L_, B_, 2), 256>>>(c1, m1, c2, m2, wmp);

    // fork: weighted GEMM on side stream, cosine chain on main stream
    cudaEventRecord(evF, 0);
    cudaStreamWaitEvent(sB, evF, 0);
    k_gemm <<<dim3(P_, B_), 256, 0, sB>>>(wmp, m1, m2, out);
    cudaEventRecord(evB, sB);

    k_gcos  <<<dim3(4, B_), 256>>>();
    k_att   <<<dim3(L_/TT, B_, 2), ATT_THR>>>(m1, m2, out);
    k_final <<<dim3(L_, B_, 2), 256>>>(wff, wfb, watt, wmatt, out);

    // join
    cudaStreamWaitEvent(0, evB, 0);
}